// round 1
// baseline (speedup 1.0000x reference)
#include <cuda_runtime.h>
#include <math.h>

#define B_  8
#define T_  1024
#define D_  768
#define H_  12
#define HD_ 64
#define BH_ (B_*H_)   /* 96 */
#define N_  (B_*T_)   /* 8192 */

// ---- scratch (static device globals; no allocation) ----
__device__ float g_q[BH_*T_*HD_];
__device__ float g_k[BH_*T_*HD_];
__device__ float g_v[BH_*T_*HD_];
__device__ float g_attn[N_*D_];
__device__ float g_ga1[BH_*T_];

// ============================================================
// GEMM: C[N_ x D_] = A[N_ x D_] @ W[D_ x D_] + bias
// BM=BN=128, BK=16, 256 threads, 8x8 register tile.
// head_layout: write out[((b*H+h)*T + t)*HD + hd] instead of row-major.
// ============================================================
__global__ __launch_bounds__(256)
void gemm_kernel(const float* __restrict__ A, const float* __restrict__ W,
                 const float* __restrict__ bias, float* __restrict__ out,
                 int head_layout)
{
    __shared__ float As[16][132];   // k-major: As[k][row]
    __shared__ float Bs[16][132];   // Bs[k][col]
    const int tid = threadIdx.x;
    const int tx = tid & 15;
    const int ty = tid >> 4;
    const int row0 = blockIdx.x * 128;
    const int col0 = blockIdx.y * 128;

    float acc[8][8];
#pragma unroll
    for (int i = 0; i < 8; i++)
#pragma unroll
        for (int j = 0; j < 8; j++) acc[i][j] = 0.f;

    for (int k0 = 0; k0 < D_; k0 += 16) {
        // A tile: 128 rows x 16 k  (512 float4, 2 per thread)
#pragma unroll
        for (int i = 0; i < 2; i++) {
            int idx = tid + i * 256;          // 0..511
            int r   = idx >> 2;               // 0..127
            int q4  = (idx & 3) * 4;          // 0,4,8,12
            float4 v = *(const float4*)(A + (size_t)(row0 + r) * D_ + k0 + q4);
            As[q4 + 0][r] = v.x; As[q4 + 1][r] = v.y;
            As[q4 + 2][r] = v.z; As[q4 + 3][r] = v.w;
        }
        // B tile: 16 k x 128 cols
#pragma unroll
        for (int i = 0; i < 2; i++) {
            int idx = tid + i * 256;
            int kk  = idx >> 5;               // 0..15
            int c4  = (idx & 31) * 4;         // 0..124
            *(float4*)(&Bs[kk][c4]) =
                *(const float4*)(W + (size_t)(k0 + kk) * D_ + col0 + c4);
        }
        __syncthreads();
#pragma unroll
        for (int k = 0; k < 16; k++) {
            float a[8], b[8];
            *(float4*)(a)     = *(const float4*)(&As[k][ty * 8]);
            *(float4*)(a + 4) = *(const float4*)(&As[k][ty * 8 + 4]);
            *(float4*)(b)     = *(const float4*)(&Bs[k][tx * 8]);
            *(float4*)(b + 4) = *(const float4*)(&Bs[k][tx * 8 + 4]);
#pragma unroll
            for (int i = 0; i < 8; i++)
#pragma unroll
                for (int j = 0; j < 8; j++) acc[i][j] += a[i] * b[j];
        }
        __syncthreads();
    }

    // epilogue (+bias), float4 stores
#pragma unroll
    for (int i = 0; i < 8; i++) {
        int row = row0 + ty * 8 + i;
        int bb  = row >> 10;         // /1024
        int tt  = row & 1023;
#pragma unroll
        for (int jj = 0; jj < 8; jj += 4) {
            int col = col0 + tx * 8 + jj;
            float4 v;
            v.x = acc[i][jj + 0] + bias[col + 0];
            v.y = acc[i][jj + 1] + bias[col + 1];
            v.z = acc[i][jj + 2] + bias[col + 2];
            v.w = acc[i][jj + 3] + bias[col + 3];
            float* dst;
            if (head_layout) {
                int hh = col >> 6, hd = col & 63;
                dst = out + ((size_t)(bb * H_ + hh) * T_ + tt) * HD_ + hd;
            } else {
                dst = out + (size_t)row * D_ + col;
            }
            *(float4*)dst = v;
        }
    }
}

// ============================================================
// Gates: one warp per (bh, t).
// s0 = sum_{j<4}(x_h . Wg[:,j] + bg[j]), s1 = same j in 4..7
// ga1 = sigmoid(s0) * (sigmoid(s1)*grep_a[h] - 1) + 2
// ============================================================
__global__ __launch_bounds__(256)
void gates_kernel(const float* __restrict__ x, const float* __restrict__ Wg,
                  const float* __restrict__ bg, const float* __restrict__ grep_a,
                  float* __restrict__ ga1)
{
    int w    = blockIdx.x * 8 + (threadIdx.x >> 5);   // 0..98303
    int lane = threadIdx.x & 31;
    int bh = w >> 10, t = w & 1023;
    int b = bh / H_, h = bh % H_;
    const float* xp = x + ((size_t)b * T_ + t) * D_ + h * HD_;

    float s0 = 0.f, s1 = 0.f;
#pragma unroll
    for (int d = lane; d < HD_; d += 32) {
        float xv = xp[d];
        const float* wg = Wg + d * 8;
        s0 += xv * (wg[0] + wg[1] + wg[2] + wg[3]);
        s1 += xv * (wg[4] + wg[5] + wg[6] + wg[7]);
    }
#pragma unroll
    for (int off = 16; off > 0; off >>= 1) {
        s0 += __shfl_xor_sync(0xffffffffu, s0, off);
        s1 += __shfl_xor_sync(0xffffffffu, s1, off);
    }
    if (lane == 0) {
        s0 += bg[0] + bg[1] + bg[2] + bg[3];
        s1 += bg[4] + bg[5] + bg[6] + bg[7];
        float ga = 1.f / (1.f + expf(-s0));
        float gb = 1.f / (1.f + expf(-s1));
        ga1[w] = ga * (gb * grep_a[h] - 1.f) + 2.f;
    }
}

// ============================================================
// Flash attention per (bh, q-tile of 64). BK=32, 256 threads.
// S[q,k] = (q.k)/8 + ga1[q]*rel_bias[bh,k,q] + mask[b,k]
// Thread (ty,tx): S tile 4q x 2k, O tile 4q x 4hd.
// Static smem: Qs 17408 + Ks 9216 + Vs 8704 + Ps 8704 + Ms 4096 = 48128 B
// ============================================================
__global__ __launch_bounds__(256)
void attn_kernel(const float* __restrict__ rel_bias,
                 const float* __restrict__ attn_mask,
                 float* __restrict__ attn_out)
{
    __shared__ float Qs[64 * 68];   // [d][q]
    __shared__ float Ks[64 * 36];   // [d][k] (k-tile 32, pad 4)
    __shared__ float Vs[32 * 68];   // [k][c]
    __shared__ float Ps[32 * 68];   // [k][q]  (also stages rel_bias tile)
    __shared__ float Ms[1024];      // mask row for this b

    const int tid = threadIdx.x;
    const int tx = tid & 15;
    const int ty = tid >> 4;
    const int q0 = blockIdx.x * 64;
    const int bh = blockIdx.y;
    const int b  = bh / H_, h = bh % H_;

    const float* qptr = g_q + (size_t)bh * T_ * HD_;
    const float* kptr = g_k + (size_t)bh * T_ * HD_;
    const float* vptr = g_v + (size_t)bh * T_ * HD_;

    // stage Q tile transposed: [d][q]
#pragma unroll
    for (int i = 0; i < 4; i++) {
        int idx = tid + i * 256;            // 0..1023
        int qq  = idx >> 4;                 // 0..63
        int d4  = (idx & 15) * 4;           // 0..60
        float4 v = *(const float4*)(qptr + (size_t)(q0 + qq) * HD_ + d4);
        Qs[(d4 + 0) * 68 + qq] = v.x; Qs[(d4 + 1) * 68 + qq] = v.y;
        Qs[(d4 + 2) * 68 + qq] = v.z; Qs[(d4 + 3) * 68 + qq] = v.w;
    }
    // mask row
    *(float4*)(&Ms[tid * 4]) = *(const float4*)(attn_mask + (size_t)b * T_ + tid * 4);

    float ga1r[4];
#pragma unroll
    for (int i = 0; i < 4; i++)
        ga1r[i] = g_ga1[(size_t)bh * T_ + q0 + ty * 4 + i];

    float m_[4], l_[4], o_[4][4];
#pragma unroll
    for (int i = 0; i < 4; i++) {
        m_[i] = -INFINITY; l_[i] = 0.f;
#pragma unroll
        for (int c = 0; c < 4; c++) o_[i][c] = 0.f;
    }
    __syncthreads();

    for (int k0 = 0; k0 < T_; k0 += 32) {
        // ---- stage rel_bias tile [k][q], K tile [d][k], V tile [k][c] ----
        const float* rbp = rel_bias + ((size_t)bh * T_ + k0) * T_ + q0;
#pragma unroll
        for (int i = 0; i < 2; i++) {
            int idx = tid + i * 256;        // 0..511
            int kk  = idx >> 4;             // 0..31
            int q4  = (idx & 15) * 4;
            *(float4*)(&Ps[kk * 68 + q4]) = *(const float4*)(rbp + (size_t)kk * T_ + q4);
        }
#pragma unroll
        for (int i = 0; i < 2; i++) {
            int idx = tid + i * 256;
            int kk  = idx >> 4;
            int d4  = (idx & 15) * 4;
            float4 kv = *(const float4*)(kptr + (size_t)(k0 + kk) * HD_ + d4);
            Ks[(d4 + 0) * 36 + kk] = kv.x; Ks[(d4 + 1) * 36 + kk] = kv.y;
            Ks[(d4 + 2) * 36 + kk] = kv.z; Ks[(d4 + 3) * 36 + kk] = kv.w;
            float4 vv = *(const float4*)(vptr + (size_t)(k0 + kk) * HD_ + d4);
            *(float4*)(&Vs[kk * 68 + d4]) = vv;
        }
        __syncthreads();

        // ---- S = (q.k)/8 + ga1*rb + mask ; acc starts at 8*bias, /8 later ----
        float acc[4][2];
#pragma unroll
        for (int i = 0; i < 4; i++)
#pragma unroll
            for (int j = 0; j < 2; j++) {
                int kk = tx * 2 + j;
                acc[i][j] = 8.f * fmaf(ga1r[i], Ps[kk * 68 + ty * 4 + i], Ms[k0 + kk]);
            }
#pragma unroll 8
        for (int d = 0; d < HD_; d++) {
            float a[4], bb[2];
            *(float4*)a  = *(const float4*)(&Qs[d * 68 + ty * 4]);
            *(float2*)bb = *(const float2*)(&Ks[d * 36 + tx * 2]);
#pragma unroll
            for (int i = 0; i < 4; i++)
#pragma unroll
                for (int j = 0; j < 2; j++) acc[i][j] += a[i] * bb[j];
        }
#pragma unroll
        for (int i = 0; i < 4; i++)
#pragma unroll
            for (int j = 0; j < 2; j++) acc[i][j] *= 0.125f;

        // ---- online softmax over this k-tile ----
        float mt[4];
#pragma unroll
        for (int i = 0; i < 4; i++) mt[i] = fmaxf(acc[i][0], acc[i][1]);
#pragma unroll
        for (int off = 8; off > 0; off >>= 1)
#pragma unroll
            for (int i = 0; i < 4; i++)
                mt[i] = fmaxf(mt[i], __shfl_xor_sync(0xffffffffu, mt[i], off, 16));

        float al[4], ls[4], p[4][2];
#pragma unroll
        for (int i = 0; i < 4; i++) {
            float mn = fmaxf(m_[i], mt[i]);
            al[i] = __expf(m_[i] - mn);
            m_[i] = mn;
            float s = 0.f;
#pragma unroll
            for (int j = 0; j < 2; j++) {
                p[i][j] = __expf(acc[i][j] - mn);
                s += p[i][j];
            }
            ls[i] = s;
        }
#pragma unroll
        for (int off = 8; off > 0; off >>= 1)
#pragma unroll
            for (int i = 0; i < 4; i++)
                ls[i] += __shfl_xor_sync(0xffffffffu, ls[i], off, 16);
#pragma unroll
        for (int i = 0; i < 4; i++) {
            l_[i] = l_[i] * al[i] + ls[i];
#pragma unroll
            for (int c = 0; c < 4; c++) o_[i][c] *= al[i];
        }
        __syncthreads();                 // everyone done reading Ps as rel_bias

        // ---- write P tile [k][q] ----
#pragma unroll
        for (int i = 0; i < 4; i++)
#pragma unroll
            for (int j = 0; j < 2; j++)
                Ps[(tx * 2 + j) * 68 + ty * 4 + i] = p[i][j];
        __syncthreads();

        // ---- O += P @ V ----
#pragma unroll 8
        for (int k = 0; k < 32; k++) {
            float a[4], v4[4];
            *(float4*)a  = *(const float4*)(&Ps[k * 68 + ty * 4]);
            *(float4*)v4 = *(const float4*)(&Vs[k * 68 + tx * 4]);
#pragma unroll
            for (int i = 0; i < 4; i++)
#pragma unroll
                for (int c = 0; c < 4; c++) o_[i][c] += a[i] * v4[c];
        }
        __syncthreads();                 // protect Ps/Vs before next stage
    }

    // ---- finalize: O /= l, write [b][t][h*64+hd] ----
#pragma unroll
    for (int i = 0; i < 4; i++) {
        float inv = 1.f / l_[i];
        float4 v;
        v.x = o_[i][0] * inv; v.y = o_[i][1] * inv;
        v.z = o_[i][2] * inv; v.w = o_[i][3] * inv;
        *(float4*)(attn_out + ((size_t)b * T_ + q0 + ty * 4 + i) * D_ + h * HD_ + tx * 4) = v;
    }
}

// ============================================================
extern "C" void kernel_launch(void* const* d_in, const int* in_sizes, int n_in,
                              void* d_out, int out_size)
{
    const float* x         = (const float*)d_in[0];
    const float* attn_mask = (const float*)d_in[1];
    const float* rel_bias  = (const float*)d_in[2];
    const float* Wq = (const float*)d_in[3];
    const float* bq = (const float*)d_in[4];
    const float* Wk = (const float*)d_in[5];
    const float* bk = (const float*)d_in[6];
    const float* Wv = (const float*)d_in[7];
    const float* bv = (const float*)d_in[8];
    const float* Wo = (const float*)d_in[9];
    const float* bo = (const float*)d_in[10];
    const float* Wg = (const float*)d_in[11];
    const float* bg = (const float*)d_in[12];
    const float* grep_a = (const float*)d_in[13];
    float* out = (float*)d_out;

    float *q, *k, *v, *attn, *ga1;
    cudaGetSymbolAddress((void**)&q,    g_q);
    cudaGetSymbolAddress((void**)&k,    g_k);
    cudaGetSymbolAddress((void**)&v,    g_v);
    cudaGetSymbolAddress((void**)&attn, g_attn);
    cudaGetSymbolAddress((void**)&ga1,  g_ga1);

    dim3 ggrid(N_ / 128, D_ / 128);   // (64, 6)

    gemm_kernel<<<ggrid, 256>>>(x, Wq, bq, q, 1);
    gemm_kernel<<<ggrid, 256>>>(x, Wk, bk, k, 1);
    gemm_kernel<<<ggrid, 256>>>(x, Wv, bv, v, 1);
    gates_kernel<<<BH_ * T_ / 8, 256>>>(x, Wg, bg, grep_a, ga1);
    attn_kernel<<<dim3(T_ / 64, BH_), 256>>>(rel_bias, attn_mask, attn);
    gemm_kernel<<<ggrid, 256>>>(attn, Wo, bo, out, 0);
}

// round 2
// speedup vs baseline: 1.7983x; 1.7983x over previous
#include <cuda_runtime.h>
#include <math.h>
#include <stdint.h>

#define B_  8
#define T_  1024
#define D_  768
#define H_  12
#define HD_ 64
#define BH_ (B_*H_)   /* 96 */
#define N_  (B_*T_)   /* 8192 */

// ---- scratch (static device globals; no allocation) ----
__device__ float g_q[BH_*T_*HD_];
__device__ float g_k[BH_*T_*HD_];
__device__ float g_v[BH_*T_*HD_];
__device__ float g_attn[N_*D_];
__device__ float g_ga1[BH_*T_];
__device__ float g_wg2[HD_*2];
__device__ float g_bg2[2];

// ---- tf32 helpers ----
__device__ __forceinline__ uint32_t f2tf(float f) {
    uint32_t u;
    asm("cvt.rna.tf32.f32 %0, %1;" : "=r"(u) : "f"(f));
    return u;
}
__device__ __forceinline__ void mma_tf32(float* d, const uint32_t* a, const uint32_t* b) {
    asm volatile(
        "mma.sync.aligned.m16n8k8.row.col.f32.tf32.tf32.f32 "
        "{%0,%1,%2,%3}, {%4,%5,%6,%7}, {%8,%9}, {%0,%1,%2,%3};\n"
        : "+f"(d[0]), "+f"(d[1]), "+f"(d[2]), "+f"(d[3])
        : "r"(a[0]), "r"(a[1]), "r"(a[2]), "r"(a[3]), "r"(b[0]), "r"(b[1]));
}

// ============================================================
// tf32 GEMM: C[N_ x D_] = A[N_ x D_] @ W[D_ x D_] + bias
// BM=128 BN=128 BK=16, 256 thr = 8 warps (4m x 2n), warp tile 32x64.
// SPLIT==3: 3xtf32 (hi*hi + hi*lo + lo*hi) ~ fp32 accuracy.
// ============================================================
template<int SPLIT>
__global__ __launch_bounds__(256)
void gemm_tf32(const float* __restrict__ A, const float* __restrict__ W,
               const float* __restrict__ bias, float* __restrict__ out,
               int head_layout)
{
    __shared__ uint32_t Ah[16][136];
    __shared__ uint32_t Bh[16][136];
    __shared__ uint32_t Al[(SPLIT==3)?16:1][(SPLIT==3)?136:1];
    __shared__ uint32_t Bl[(SPLIT==3)?16:1][(SPLIT==3)?136:1];

    const int tid = threadIdx.x;
    const int w   = tid >> 5;
    const int lane= tid & 31;
    const int g   = lane >> 2;     // 0..7
    const int q4  = lane & 3;      // 0..3
    const int wm  = (w & 3) * 32;  // warp m offset
    const int wn  = (w >> 2) * 64; // warp n offset
    const int row0 = blockIdx.x * 128;
    const int col0 = blockIdx.y * 128;

    float acc[2][8][4];
#pragma unroll
    for (int i = 0; i < 2; i++)
#pragma unroll
        for (int f = 0; f < 8; f++)
#pragma unroll
            for (int e = 0; e < 4; e++) acc[i][f][e] = 0.f;

    for (int k0 = 0; k0 < D_; k0 += 16) {
        // stage A tile (128 x 16) -> Ah/Al [k][m]
#pragma unroll
        for (int i = 0; i < 2; i++) {
            int idx = tid + i * 256;            // 0..511
            int r   = idx >> 2;                 // 0..127
            int k4  = (idx & 3) * 4;
            float4 v = *(const float4*)(A + (size_t)(row0 + r) * D_ + k0 + k4);
            float vv[4] = {v.x, v.y, v.z, v.w};
#pragma unroll
            for (int j = 0; j < 4; j++) {
                uint32_t hi = f2tf(vv[j]);
                Ah[k4 + j][r] = hi;
                if (SPLIT == 3) Al[k4 + j][r] = f2tf(vv[j] - __uint_as_float(hi));
            }
        }
        // stage B tile (16 x 128) -> Bh/Bl [k][n]
#pragma unroll
        for (int i = 0; i < 2; i++) {
            int idx = tid + i * 256;
            int kk  = idx >> 5;                 // 0..15
            int c4  = (idx & 31) * 4;
            float4 v = *(const float4*)(W + (size_t)(k0 + kk) * D_ + col0 + c4);
            float vv[4] = {v.x, v.y, v.z, v.w};
#pragma unroll
            for (int j = 0; j < 4; j++) {
                uint32_t hi = f2tf(vv[j]);
                Bh[kk][c4 + j] = hi;
                if (SPLIT == 3) Bl[kk][c4 + j] = f2tf(vv[j] - __uint_as_float(hi));
            }
        }
        __syncthreads();

#pragma unroll
        for (int s = 0; s < 2; s++) {
            uint32_t ah[2][4], al[2][4];
#pragma unroll
            for (int i = 0; i < 2; i++) {
                int r0 = wm + 16 * i + g;
                int kc = 8 * s + q4;
                ah[i][0] = Ah[kc][r0];     ah[i][1] = Ah[kc][r0 + 8];
                ah[i][2] = Ah[kc + 4][r0]; ah[i][3] = Ah[kc + 4][r0 + 8];
                if (SPLIT == 3) {
                    al[i][0] = Al[kc][r0];     al[i][1] = Al[kc][r0 + 8];
                    al[i][2] = Al[kc + 4][r0]; al[i][3] = Al[kc + 4][r0 + 8];
                }
            }
            uint32_t bh[8][2], bl[8][2];
#pragma unroll
            for (int f = 0; f < 8; f++) {
                int n0 = wn + 8 * f + g;
                int kc = 8 * s + q4;
                bh[f][0] = Bh[kc][n0]; bh[f][1] = Bh[kc + 4][n0];
                if (SPLIT == 3) { bl[f][0] = Bl[kc][n0]; bl[f][1] = Bl[kc + 4][n0]; }
            }
#pragma unroll
            for (int i = 0; i < 2; i++)
#pragma unroll
                for (int f = 0; f < 8; f++) {
                    mma_tf32(acc[i][f], ah[i], bh[f]);
                    if (SPLIT == 3) {
                        mma_tf32(acc[i][f], ah[i], bl[f]);
                        mma_tf32(acc[i][f], al[i], bh[f]);
                    }
                }
        }
        __syncthreads();
    }

    // epilogue: +bias, write (head layout or row-major), float2 stores
#pragma unroll
    for (int i = 0; i < 2; i++) {
#pragma unroll
        for (int f = 0; f < 8; f++) {
            int col = col0 + wn + 8 * f + 2 * q4;
            float b0 = bias[col], b1 = bias[col + 1];
#pragma unroll
            for (int half = 0; half < 2; half++) {
                int row = row0 + wm + 16 * i + g + 8 * half;
                float2 v;
                v.x = acc[i][f][2 * half + 0] + b0;
                v.y = acc[i][f][2 * half + 1] + b1;
                float* dst;
                if (head_layout) {
                    int bb = row >> 10, tt = row & 1023;
                    int hh = col >> 6, hd = col & 63;
                    dst = out + ((size_t)(bb * H_ + hh) * T_ + tt) * HD_ + hd;
                } else {
                    dst = out + (size_t)row * D_ + col;
                }
                *(float2*)dst = v;
            }
        }
    }
}

// ============================================================
// Precompute Wg row-sums (64 x 2) once.
// ============================================================
__global__ void wg2_kernel(const float* __restrict__ Wg, const float* __restrict__ bg)
{
    int d = threadIdx.x;   // 0..63
    const float* wg = Wg + d * 8;
    g_wg2[d * 2 + 0] = wg[0] + wg[1] + wg[2] + wg[3];
    g_wg2[d * 2 + 1] = wg[4] + wg[5] + wg[6] + wg[7];
    if (d == 0) {
        g_bg2[0] = bg[0] + bg[1] + bg[2] + bg[3];
        g_bg2[1] = bg[4] + bg[5] + bg[6] + bg[7];
    }
}

// ============================================================
// Gates: warp per (bh,t) using precomputed wg2.
// ============================================================
__global__ __launch_bounds__(256)
void gates_kernel(const float* __restrict__ x, const float* __restrict__ grep_a,
                  float* __restrict__ ga1)
{
    int w    = blockIdx.x * 8 + (threadIdx.x >> 5);
    int lane = threadIdx.x & 31;
    int bh = w >> 10, t = w & 1023;
    int b = bh / H_, h = bh % H_;
    const float* xp = x + ((size_t)b * T_ + t) * D_ + h * HD_;

    float s0 = 0.f, s1 = 0.f;
#pragma unroll
    for (int d = lane; d < HD_; d += 32) {
        float xv = xp[d];
        s0 += xv * g_wg2[d * 2 + 0];
        s1 += xv * g_wg2[d * 2 + 1];
    }
#pragma unroll
    for (int off = 16; off > 0; off >>= 1) {
        s0 += __shfl_xor_sync(0xffffffffu, s0, off);
        s1 += __shfl_xor_sync(0xffffffffu, s1, off);
    }
    if (lane == 0) {
        s0 += g_bg2[0];
        s1 += g_bg2[1];
        float ga = 1.f / (1.f + expf(-s0));
        float gb = 1.f / (1.f + expf(-s1));
        ga1[w] = ga * (gb * grep_a[h] - 1.f) + 2.f;
    }
}

// ============================================================
// Flash attention, tf32 mma. q-tile 128, k-tile 32, 256 thr (8 warps).
// Warp w owns q rows [16w, 16w+16). Q frags live in registers.
// S = (Q.K^T)/8 + ga1*rel_bias^T + mask ; online softmax ; O += P@V.
// smem: Ks[32][68]u + Vs[32][72]u + U (RB 32x132 / P 128x36 union) + Ms[32]
// ============================================================
__global__ __launch_bounds__(256, 2)
void attn_kernel(const float* __restrict__ rel_bias,
                 const float* __restrict__ attn_mask,
                 float* __restrict__ attn_out)
{
    __shared__ uint32_t Ks[32][68];
    __shared__ uint32_t Vs[32][72];
    __shared__ float    U[4608];          // RB: U[k*132+q] ; P: ((u32*)U)[r*36+c]
    __shared__ float    Ms[32];

    const int tid  = threadIdx.x;
    const int w    = tid >> 5;
    const int lane = tid & 31;
    const int g    = lane >> 2;      // 0..7
    const int q4   = lane & 3;       // 0..3
    const int qb   = 16 * w;         // warp q-row base (within 128-tile)
    const int q0   = blockIdx.x * 128;
    const int bh   = blockIdx.y;
    const int b    = bh / H_, h = bh % H_;

    const float* qptr = g_q + (size_t)bh * T_ * HD_;
    const float* kptr = g_k + (size_t)bh * T_ * HD_;
    const float* vptr = g_v + (size_t)bh * T_ * HD_;
    uint32_t* Pp = (uint32_t*)U;

    const int r0 = qb + g;       // local q rows owned by this thread
    const int r1 = qb + g + 8;

    // Q fragments (tf32) — loaded once, reused for all 32 k-tiles
    uint32_t qf[8][4];
    {
        const float* qa = qptr + (size_t)(q0 + r0) * HD_;
        const float* qc = qptr + (size_t)(q0 + r1) * HD_;
#pragma unroll
        for (int s = 0; s < 8; s++) {
            qf[s][0] = f2tf(qa[q4 + 8 * s]);
            qf[s][1] = f2tf(qc[q4 + 8 * s]);
            qf[s][2] = f2tf(qa[q4 + 4 + 8 * s]);
            qf[s][3] = f2tf(qc[q4 + 4 + 8 * s]);
        }
    }
    const float ga0 = g_ga1[(size_t)bh * T_ + q0 + r0];
    const float ga1v= g_ga1[(size_t)bh * T_ + q0 + r1];

    float m_[2] = {-INFINITY, -INFINITY};
    float l_[2] = {0.f, 0.f};
    float oacc[8][4];
#pragma unroll
    for (int f = 0; f < 8; f++)
#pragma unroll
        for (int e = 0; e < 4; e++) oacc[f][e] = 0.f;

    for (int k0 = 0; k0 < T_; k0 += 32) {
        // ---- stage K, V (tf32), rel_bias tile, mask ----
#pragma unroll
        for (int i = 0; i < 2; i++) {
            int idx = tid + i * 256;          // 0..511
            int kk  = idx >> 4;               // 0..31
            int d4  = (idx & 15) * 4;
            float4 kv = *(const float4*)(kptr + (size_t)(k0 + kk) * HD_ + d4);
            Ks[kk][d4+0] = f2tf(kv.x); Ks[kk][d4+1] = f2tf(kv.y);
            Ks[kk][d4+2] = f2tf(kv.z); Ks[kk][d4+3] = f2tf(kv.w);
            float4 vv = *(const float4*)(vptr + (size_t)(k0 + kk) * HD_ + d4);
            Vs[kk][d4+0] = f2tf(vv.x); Vs[kk][d4+1] = f2tf(vv.y);
            Vs[kk][d4+2] = f2tf(vv.z); Vs[kk][d4+3] = f2tf(vv.w);
        }
        {
            const float* rbp = rel_bias + ((size_t)bh * T_ + k0) * T_ + q0;
#pragma unroll
            for (int i = 0; i < 4; i++) {
                int idx = tid + i * 256;      // 0..1023
                int kk  = idx >> 5;           // 0..31
                int qq  = (idx & 31) * 4;
                *(float4*)(&U[kk * 132 + qq]) = *(const float4*)(rbp + (size_t)kk * T_ + qq);
            }
        }
        if (tid < 32) Ms[tid] = attn_mask[(size_t)b * T_ + k0 + tid];
        __syncthreads();

        // ---- S acc init: 8*(ga1*rb + mask); mma adds dot; *0.125 after ----
        float sacc[4][4];
#pragma unroll
        for (int f = 0; f < 4; f++) {
            int c0 = 8 * f + 2 * q4;
            sacc[f][0] = 8.f * fmaf(ga0,  U[c0 * 132 + r0],       Ms[c0]);
            sacc[f][1] = 8.f * fmaf(ga0,  U[(c0 + 1) * 132 + r0], Ms[c0 + 1]);
            sacc[f][2] = 8.f * fmaf(ga1v, U[c0 * 132 + r1],       Ms[c0]);
            sacc[f][3] = 8.f * fmaf(ga1v, U[(c0 + 1) * 132 + r1], Ms[c0 + 1]);
        }
#pragma unroll
        for (int s = 0; s < 8; s++) {
            uint32_t bf[4][2];
#pragma unroll
            for (int f = 0; f < 4; f++) {
                bf[f][0] = Ks[8 * f + g][q4 + 8 * s];
                bf[f][1] = Ks[8 * f + g][q4 + 4 + 8 * s];
            }
#pragma unroll
            for (int f = 0; f < 4; f++) mma_tf32(sacc[f], qf[s], bf[f]);
        }
#pragma unroll
        for (int f = 0; f < 4; f++)
#pragma unroll
            for (int e = 0; e < 4; e++) sacc[f][e] *= 0.125f;

        __syncthreads();   // all RB reads done before P overwrites U

        // ---- online softmax (rows warp-local; reduce over 4-lane quad) ----
        float mt0 = sacc[0][0], mt1 = sacc[0][2];
#pragma unroll
        for (int f = 0; f < 4; f++) {
            mt0 = fmaxf(mt0, fmaxf(sacc[f][0], sacc[f][1]));
            mt1 = fmaxf(mt1, fmaxf(sacc[f][2], sacc[f][3]));
        }
        mt0 = fmaxf(mt0, __shfl_xor_sync(0xffffffffu, mt0, 1));
        mt0 = fmaxf(mt0, __shfl_xor_sync(0xffffffffu, mt0, 2));
        mt1 = fmaxf(mt1, __shfl_xor_sync(0xffffffffu, mt1, 1));
        mt1 = fmaxf(mt1, __shfl_xor_sync(0xffffffffu, mt1, 2));

        float mn0 = fmaxf(m_[0], mt0), mn1 = fmaxf(m_[1], mt1);
        float al0 = __expf(m_[0] - mn0), al1 = __expf(m_[1] - mn1);
        m_[0] = mn0; m_[1] = mn1;

        float ls0 = 0.f, ls1 = 0.f;
#pragma unroll
        for (int f = 0; f < 4; f++) {
            sacc[f][0] = __expf(sacc[f][0] - mn0);
            sacc[f][1] = __expf(sacc[f][1] - mn0);
            sacc[f][2] = __expf(sacc[f][2] - mn1);
            sacc[f][3] = __expf(sacc[f][3] - mn1);
            ls0 += sacc[f][0] + sacc[f][1];
            ls1 += sacc[f][2] + sacc[f][3];
        }
        ls0 += __shfl_xor_sync(0xffffffffu, ls0, 1);
        ls0 += __shfl_xor_sync(0xffffffffu, ls0, 2);
        ls1 += __shfl_xor_sync(0xffffffffu, ls1, 1);
        ls1 += __shfl_xor_sync(0xffffffffu, ls1, 2);
        l_[0] = l_[0] * al0 + ls0;
        l_[1] = l_[1] * al1 + ls1;
#pragma unroll
        for (int f = 0; f < 8; f++) {
            oacc[f][0] *= al0; oacc[f][1] *= al0;
            oacc[f][2] *= al1; oacc[f][3] *= al1;
        }

        // ---- stage P (tf32) into warp-private rows of U ----
#pragma unroll
        for (int f = 0; f < 4; f++) {
            int c0 = 8 * f + 2 * q4;
            Pp[r0 * 36 + c0]     = f2tf(sacc[f][0]);
            Pp[r0 * 36 + c0 + 1] = f2tf(sacc[f][1]);
            Pp[r1 * 36 + c0]     = f2tf(sacc[f][2]);
            Pp[r1 * 36 + c0 + 1] = f2tf(sacc[f][3]);
        }
        __syncwarp();

        // ---- O += P @ V ----
#pragma unroll
        for (int s = 0; s < 4; s++) {
            uint32_t pa[4];
            pa[0] = Pp[r0 * 36 + q4 + 8 * s];
            pa[1] = Pp[r1 * 36 + q4 + 8 * s];
            pa[2] = Pp[r0 * 36 + q4 + 4 + 8 * s];
            pa[3] = Pp[r1 * 36 + q4 + 4 + 8 * s];
#pragma unroll
            for (int f = 0; f < 8; f++) {
                uint32_t vb[2];
                vb[0] = Vs[8 * s + q4][8 * f + g];
                vb[1] = Vs[8 * s + q4 + 4][8 * f + g];
                mma_tf32(oacc[f], pa, vb);
            }
        }
        __syncthreads();   // before next-iter staging overwrites Ks/Vs/U
    }

    // ---- finalize: O /= l ; write [b][t][h*64+hd] ----
    float inv0 = 1.f / l_[0], inv1 = 1.f / l_[1];
#pragma unroll
    for (int f = 0; f < 8; f++) {
        int c = 8 * f + 2 * q4;
        float2 v0; v0.x = oacc[f][0] * inv0; v0.y = oacc[f][1] * inv0;
        float2 v1; v1.x = oacc[f][2] * inv1; v1.y = oacc[f][3] * inv1;
        *(float2*)(attn_out + ((size_t)b * T_ + q0 + r0) * D_ + h * HD_ + c) = v0;
        *(float2*)(attn_out + ((size_t)b * T_ + q0 + r1) * D_ + h * HD_ + c) = v1;
    }
}

// ============================================================
extern "C" void kernel_launch(void* const* d_in, const int* in_sizes, int n_in,
                              void* d_out, int out_size)
{
    const float* x         = (const float*)d_in[0];
    const float* attn_mask = (const float*)d_in[1];
    const float* rel_bias  = (const float*)d_in[2];
    const float* Wq = (const float*)d_in[3];
    const float* bq = (const float*)d_in[4];
    const float* Wk = (const float*)d_in[5];
    const float* bk = (const float*)d_in[6];
    const float* Wv = (const float*)d_in[7];
    const float* bv = (const float*)d_in[8];
    const float* Wo = (const float*)d_in[9];
    const float* bo = (const float*)d_in[10];
    const float* Wg = (const float*)d_in[11];
    const float* bg = (const float*)d_in[12];
    const float* grep_a = (const float*)d_in[13];
    float* out = (float*)d_out;

    float *q, *k, *v, *attn, *ga1;
    cudaGetSymbolAddress((void**)&q,    g_q);
    cudaGetSymbolAddress((void**)&k,    g_k);
    cudaGetSymbolAddress((void**)&v,    g_v);
    cudaGetSymbolAddress((void**)&attn, g_attn);
    cudaGetSymbolAddress((void**)&ga1,  g_ga1);

    dim3 ggrid(N_ / 128, D_ / 128);   // (64, 6)

    gemm_tf32<1><<<ggrid, 256>>>(x, Wq, bq, q, 1);
    gemm_tf32<1><<<ggrid, 256>>>(x, Wk, bk, k, 1);
    gemm_tf32<3><<<ggrid, 256>>>(x, Wv, bv, v, 1);
    wg2_kernel<<<1, 64>>>(Wg, bg);
    gates_kernel<<<BH_ * T_ / 8, 256>>>(x, grep_a, ga1);
    attn_kernel<<<dim3(T_ / 128, BH_), 256>>>(rel_bias, attn_mask, attn);
    gemm_tf32<3><<<ggrid, 256>>>(attn, Wo, bo, out, 0);
}

// round 3
// speedup vs baseline: 2.5595x; 1.4233x over previous
#include <cuda_runtime.h>
#include <math.h>
#include <stdint.h>

#define B_  8
#define T_  1024
#define D_  768
#define H_  12
#define HD_ 64
#define BH_ (B_*H_)   /* 96 */
#define N_  (B_*T_)   /* 8192 */

// ---- scratch (static device globals; no allocation) ----
__device__ uint32_t g_xhi[N_*D_];
__device__ uint32_t g_wqh[D_*D_];
__device__ uint32_t g_wkh[D_*D_];
__device__ uint32_t g_wvh[D_*D_];
__device__ uint32_t g_woh[D_*D_];
__device__ uint32_t g_wol[D_*D_];
__device__ uint32_t g_q[BH_*T_*HD_];   // tf32
__device__ uint32_t g_k[BH_*T_*HD_];   // tf32
__device__ uint32_t g_v[BH_*T_*HD_];   // tf32
__device__ uint32_t g_ahi[N_*D_];      // attn out hi (tf32)
__device__ uint32_t g_alo[N_*D_];      // attn out lo (tf32)
__device__ float    g_ga1[BH_*T_];
__device__ float    g_wg2[HD_*2];
__device__ float    g_bg2[2];

// ---- helpers ----
__device__ __forceinline__ uint32_t f2tf(float f) {
    uint32_t u;
    asm("cvt.rna.tf32.f32 %0, %1;" : "=r"(u) : "f"(f));
    return u;
}
__device__ __forceinline__ void mma_tf32(float* d, const uint32_t* a, const uint32_t* b) {
    asm volatile(
        "mma.sync.aligned.m16n8k8.row.col.f32.tf32.tf32.f32 "
        "{%0,%1,%2,%3}, {%4,%5,%6,%7}, {%8,%9}, {%0,%1,%2,%3};\n"
        : "+f"(d[0]), "+f"(d[1]), "+f"(d[2]), "+f"(d[3])
        : "r"(a[0]), "r"(a[1]), "r"(a[2]), "r"(a[3]), "r"(b[0]), "r"(b[1]));
}
__device__ __forceinline__ uint32_t saddr(const void* p) {
    return (uint32_t)__cvta_generic_to_shared(p);
}
__device__ __forceinline__ void cp16(uint32_t s, const void* g) {
    asm volatile("cp.async.cg.shared.global [%0], [%1], 16;\n" :: "r"(s), "l"(g));
}
#define CP_COMMIT() asm volatile("cp.async.commit_group;\n")
#define CP_WAIT1()  asm volatile("cp.async.wait_group 1;\n")
#define CP_WAIT0()  asm volatile("cp.async.wait_group 0;\n")

// ============================================================
// Preconversion kernels (run once, tiny)
// ============================================================
__global__ void conv_hi(const float4* __restrict__ in, uint4* __restrict__ hi, int n4)
{
    int i = blockIdx.x * blockDim.x + threadIdx.x;
    if (i >= n4) return;
    float4 v = in[i];
    uint4 h;
    h.x = f2tf(v.x); h.y = f2tf(v.y); h.z = f2tf(v.z); h.w = f2tf(v.w);
    hi[i] = h;
}
__global__ void conv_hilo(const float4* __restrict__ in, uint4* __restrict__ hi,
                          uint4* __restrict__ lo, int n4)
{
    int i = blockIdx.x * blockDim.x + threadIdx.x;
    if (i >= n4) return;
    float4 v = in[i];
    uint4 h, l;
    h.x = f2tf(v.x); l.x = f2tf(v.x - __uint_as_float(h.x));
    h.y = f2tf(v.y); l.y = f2tf(v.y - __uint_as_float(h.y));
    h.z = f2tf(v.z); l.z = f2tf(v.z - __uint_as_float(h.z));
    h.w = f2tf(v.w); l.w = f2tf(v.w - __uint_as_float(h.w));
    hi[i] = h; lo[i] = l;
}

// ============================================================
// SPLIT1 GEMM (pre-tf32 operands): out = tf32(A@W + bias), head layout.
// BM=128 BN=128 BK=16 double-buffered cp.async. 8 warps 2x4, tile 64x32.
// ============================================================
__global__ __launch_bounds__(256, 2)
void gemm_s1(const uint32_t* __restrict__ A, const uint32_t* __restrict__ W,
             const float* __restrict__ bias, uint32_t* __restrict__ out)
{
    __shared__ __align__(16) uint32_t As[2][128][20];   // [buf][m][k]
    __shared__ __align__(16) uint32_t Bs[2][16][136];   // [buf][k][n]

    const int tid = threadIdx.x;
    const int w = tid >> 5, lane = tid & 31, g = lane >> 2, q4 = lane & 3;
    const int wm = (w & 1) * 64, wn = (w >> 1) * 32;
    const int row0 = blockIdx.x * 128, col0 = blockIdx.y * 128;

    float acc[4][4][4];
#pragma unroll
    for (int i = 0; i < 4; i++)
#pragma unroll
        for (int f = 0; f < 4; f++)
#pragma unroll
            for (int e = 0; e < 4; e++) acc[i][f][e] = 0.f;

    // stage kb=0
#pragma unroll
    for (int i = 0; i < 2; i++) {
        int idx = tid + i * 256;
        int m = idx >> 2, kc = (idx & 3) * 4;
        cp16(saddr(&As[0][m][kc]), A + (size_t)(row0 + m) * D_ + kc);
        int kk = idx >> 5, n4 = (idx & 31) * 4;
        cp16(saddr(&Bs[0][kk][n4]), W + (size_t)kk * D_ + col0 + n4);
    }
    CP_COMMIT();

    for (int kb = 0; kb < 48; kb++) {
        if (kb < 47) {
            int k0 = (kb + 1) * 16, bf = (kb + 1) & 1;
#pragma unroll
            for (int i = 0; i < 2; i++) {
                int idx = tid + i * 256;
                int m = idx >> 2, kc = (idx & 3) * 4;
                cp16(saddr(&As[bf][m][kc]), A + (size_t)(row0 + m) * D_ + k0 + kc);
                int kk = idx >> 5, n4 = (idx & 31) * 4;
                cp16(saddr(&Bs[bf][kk][n4]), W + (size_t)(k0 + kk) * D_ + col0 + n4);
            }
            CP_COMMIT();
            CP_WAIT1();
        } else {
            CP_WAIT0();
        }
        __syncthreads();
        const int b = kb & 1;
#pragma unroll
        for (int s = 0; s < 2; s++) {
            int kc = 8 * s + q4;
            uint32_t af[4][4], bf2[4][2];
#pragma unroll
            for (int i = 0; i < 4; i++) {
                int r = wm + 16 * i + g;
                af[i][0] = As[b][r][kc];     af[i][1] = As[b][r + 8][kc];
                af[i][2] = As[b][r][kc + 4]; af[i][3] = As[b][r + 8][kc + 4];
            }
#pragma unroll
            for (int f = 0; f < 4; f++) {
                int n = wn + 8 * f + g;
                bf2[f][0] = Bs[b][kc][n]; bf2[f][1] = Bs[b][kc + 4][n];
            }
#pragma unroll
            for (int i = 0; i < 4; i++)
#pragma unroll
                for (int f = 0; f < 4; f++) mma_tf32(acc[i][f], af[i], bf2[f]);
        }
        __syncthreads();
    }

    // epilogue: +bias, tf32, head layout [bh][t][hd]
#pragma unroll
    for (int i = 0; i < 4; i++)
#pragma unroll
        for (int f = 0; f < 4; f++) {
            int col = col0 + wn + 8 * f + 2 * q4;
            float b0 = bias[col], b1 = bias[col + 1];
            int hh = col >> 6, hd = col & 63;
#pragma unroll
            for (int half = 0; half < 2; half++) {
                int row = row0 + wm + 16 * i + g + 8 * half;
                int bb = row >> 10, tt = row & 1023;
                uint2 u;
                u.x = f2tf(acc[i][f][2 * half + 0] + b0);
                u.y = f2tf(acc[i][f][2 * half + 1] + b1);
                *(uint2*)(out + ((size_t)(bb * H_ + hh) * T_ + tt) * HD_ + hd) = u;
            }
        }
}

// ============================================================
// SPLIT3 GEMM (hi/lo pre-split operands): out = f32(A@W + bias), row-major.
// BM=128 BN=128 BK=8 double-buffered cp.async. 3 mmas per frag pair.
// ============================================================
__global__ __launch_bounds__(256, 2)
void gemm_s3(const uint32_t* __restrict__ Ahi, const uint32_t* __restrict__ Alo,
             const uint32_t* __restrict__ Whi, const uint32_t* __restrict__ Wlo,
             const float* __restrict__ bias, float* __restrict__ out)
{
    __shared__ __align__(16) uint32_t As[2][2][128][12];  // [buf][hi/lo][m][k]
    __shared__ __align__(16) uint32_t Bs[2][2][8][136];   // [buf][hi/lo][k][n]

    const int tid = threadIdx.x;
    const int w = tid >> 5, lane = tid & 31, g = lane >> 2, q4 = lane & 3;
    const int wm = (w & 1) * 64, wn = (w >> 1) * 32;
    const int row0 = blockIdx.x * 128, col0 = blockIdx.y * 128;

    float acc[4][4][4];
#pragma unroll
    for (int i = 0; i < 4; i++)
#pragma unroll
        for (int f = 0; f < 4; f++)
#pragma unroll
            for (int e = 0; e < 4; e++) acc[i][f][e] = 0.f;

    {   // stage kb=0
        int m = tid >> 1, kc = (tid & 1) * 4;
        cp16(saddr(&As[0][0][m][kc]), Ahi + (size_t)(row0 + m) * D_ + kc);
        cp16(saddr(&As[0][1][m][kc]), Alo + (size_t)(row0 + m) * D_ + kc);
        int kk = tid >> 5, n4 = (tid & 31) * 4;
        cp16(saddr(&Bs[0][0][kk][n4]), Whi + (size_t)kk * D_ + col0 + n4);
        cp16(saddr(&Bs[0][1][kk][n4]), Wlo + (size_t)kk * D_ + col0 + n4);
        CP_COMMIT();
    }
    for (int kb = 0; kb < 96; kb++) {
        if (kb < 95) {
            int k0 = (kb + 1) * 8, bf = (kb + 1) & 1;
            int m = tid >> 1, kc = (tid & 1) * 4;
            cp16(saddr(&As[bf][0][m][kc]), Ahi + (size_t)(row0 + m) * D_ + k0 + kc);
            cp16(saddr(&As[bf][1][m][kc]), Alo + (size_t)(row0 + m) * D_ + k0 + kc);
            int kk = tid >> 5, n4 = (tid & 31) * 4;
            cp16(saddr(&Bs[bf][0][kk][n4]), Whi + (size_t)(k0 + kk) * D_ + col0 + n4);
            cp16(saddr(&Bs[bf][1][kk][n4]), Wlo + (size_t)(k0 + kk) * D_ + col0 + n4);
            CP_COMMIT();
            CP_WAIT1();
        } else {
            CP_WAIT0();
        }
        __syncthreads();
        const int b = kb & 1;
        uint32_t ah[4][4], al[4][4], bh[4][2], bl[4][2];
#pragma unroll
        for (int i = 0; i < 4; i++) {
            int r = wm + 16 * i + g;
            ah[i][0] = As[b][0][r][q4];     ah[i][1] = As[b][0][r + 8][q4];
            ah[i][2] = As[b][0][r][q4 + 4]; ah[i][3] = As[b][0][r + 8][q4 + 4];
            al[i][0] = As[b][1][r][q4];     al[i][1] = As[b][1][r + 8][q4];
            al[i][2] = As[b][1][r][q4 + 4]; al[i][3] = As[b][1][r + 8][q4 + 4];
        }
#pragma unroll
        for (int f = 0; f < 4; f++) {
            int n = wn + 8 * f + g;
            bh[f][0] = Bs[b][0][q4][n]; bh[f][1] = Bs[b][0][q4 + 4][n];
            bl[f][0] = Bs[b][1][q4][n]; bl[f][1] = Bs[b][1][q4 + 4][n];
        }
#pragma unroll
        for (int i = 0; i < 4; i++)
#pragma unroll
            for (int f = 0; f < 4; f++) {
                mma_tf32(acc[i][f], ah[i], bh[f]);
                mma_tf32(acc[i][f], ah[i], bl[f]);
                mma_tf32(acc[i][f], al[i], bh[f]);
            }
        __syncthreads();
    }

#pragma unroll
    for (int i = 0; i < 4; i++)
#pragma unroll
        for (int f = 0; f < 4; f++) {
            int col = col0 + wn + 8 * f + 2 * q4;
            float b0 = bias[col], b1 = bias[col + 1];
#pragma unroll
            for (int half = 0; half < 2; half++) {
                int row = row0 + wm + 16 * i + g + 8 * half;
                float2 v;
                v.x = acc[i][f][2 * half + 0] + b0;
                v.y = acc[i][f][2 * half + 1] + b1;
                *(float2*)(out + (size_t)row * D_ + col) = v;
            }
        }
}

// ============================================================
// Wg row-sums + gates
// ============================================================
__global__ void wg2_kernel(const float* __restrict__ Wg, const float* __restrict__ bg)
{
    int d = threadIdx.x;
    const float* wg = Wg + d * 8;
    g_wg2[d * 2 + 0] = wg[0] + wg[1] + wg[2] + wg[3];
    g_wg2[d * 2 + 1] = wg[4] + wg[5] + wg[6] + wg[7];
    if (d == 0) {
        g_bg2[0] = bg[0] + bg[1] + bg[2] + bg[3];
        g_bg2[1] = bg[4] + bg[5] + bg[6] + bg[7];
    }
}
__global__ __launch_bounds__(256)
void gates_kernel(const float* __restrict__ x, const float* __restrict__ grep_a,
                  float* __restrict__ ga1)
{
    int w    = blockIdx.x * 8 + (threadIdx.x >> 5);
    int lane = threadIdx.x & 31;
    int bh = w >> 10, t = w & 1023;
    int b = bh / H_, h = bh % H_;
    const float* xp = x + ((size_t)b * T_ + t) * D_ + h * HD_;

    float s0 = 0.f, s1 = 0.f;
#pragma unroll
    for (int d = lane; d < HD_; d += 32) {
        float xv = xp[d];
        s0 += xv * g_wg2[d * 2 + 0];
        s1 += xv * g_wg2[d * 2 + 1];
    }
#pragma unroll
    for (int off = 16; off > 0; off >>= 1) {
        s0 += __shfl_xor_sync(0xffffffffu, s0, off);
        s1 += __shfl_xor_sync(0xffffffffu, s1, off);
    }
    if (lane == 0) {
        s0 += g_bg2[0];
        s1 += g_bg2[1];
        float ga = 1.f / (1.f + expf(-s0));
        float gb = 1.f / (1.f + expf(-s1));
        ga1[w] = ga * (gb * grep_a[h] - 1.f) + 2.f;
    }
}

// ============================================================
// Flash attention (q-tile 128, k-tile 32, 8 warps). q/k/v pre-tf32.
// Epilogue writes hi/lo split for the O-proj.
// ============================================================
__global__ __launch_bounds__(256, 2)
void attn_kernel(const float* __restrict__ rel_bias,
                 const float* __restrict__ attn_mask)
{
    __shared__ __align__(16) uint32_t Ks[32][68];
    __shared__ __align__(16) uint32_t Vs[32][72];
    __shared__ __align__(16) float    U[4608];    // RB [k][132] ; P overlay [q][36] u32
    __shared__ float Ms[32];

    const int tid  = threadIdx.x;
    const int w    = tid >> 5;
    const int lane = tid & 31;
    const int g    = lane >> 2;
    const int q4   = lane & 3;
    const int qb   = 16 * w;
    const int q0   = blockIdx.x * 128;
    const int bh   = blockIdx.y;
    const int b    = bh / H_, h = bh % H_;

    const uint32_t* qptr = g_q + (size_t)bh * T_ * HD_;
    const uint32_t* kptr = g_k + (size_t)bh * T_ * HD_;
    const uint32_t* vptr = g_v + (size_t)bh * T_ * HD_;
    uint32_t* Pp = (uint32_t*)U;

    const int r0 = qb + g;
    const int r1 = qb + g + 8;

    uint32_t qf[8][4];
    {
        const uint32_t* qa = qptr + (size_t)(q0 + r0) * HD_;
        const uint32_t* qc = qptr + (size_t)(q0 + r1) * HD_;
#pragma unroll
        for (int s = 0; s < 8; s++) {
            qf[s][0] = qa[q4 + 8 * s];
            qf[s][1] = qc[q4 + 8 * s];
            qf[s][2] = qa[q4 + 4 + 8 * s];
            qf[s][3] = qc[q4 + 4 + 8 * s];
        }
    }
    const float ga0  = g_ga1[(size_t)bh * T_ + q0 + r0];
    const float ga1v = g_ga1[(size_t)bh * T_ + q0 + r1];

    float m_[2] = {-INFINITY, -INFINITY};
    float l_[2] = {0.f, 0.f};
    float oacc[8][4];
#pragma unroll
    for (int f = 0; f < 8; f++)
#pragma unroll
        for (int e = 0; e < 4; e++) oacc[f][e] = 0.f;

    for (int k0 = 0; k0 < T_; k0 += 32) {
        // ---- stage K, V, rel_bias via cp.async; mask plain ----
#pragma unroll
        for (int i = 0; i < 2; i++) {
            int idx = tid + i * 256;
            int kk  = idx >> 4, d4 = (idx & 15) * 4;
            cp16(saddr(&Ks[kk][d4]), kptr + (size_t)(k0 + kk) * HD_ + d4);
            cp16(saddr(&Vs[kk][d4]), vptr + (size_t)(k0 + kk) * HD_ + d4);
        }
        {
            const float* rbp = rel_bias + ((size_t)bh * T_ + k0) * T_ + q0;
#pragma unroll
            for (int i = 0; i < 4; i++) {
                int idx = tid + i * 256;
                int kk  = idx >> 5, qq = (idx & 31) * 4;
                cp16(saddr(&U[kk * 132 + qq]), rbp + (size_t)kk * T_ + qq);
            }
        }
        if (tid < 32) Ms[tid] = attn_mask[(size_t)b * T_ + k0 + tid];
        CP_COMMIT();
        CP_WAIT0();
        __syncthreads();

        // ---- S = 8*(ga*rb + mask) via init, += Q.K, *0.125 ----
        float sacc[4][4];
#pragma unroll
        for (int f = 0; f < 4; f++) {
            int c0 = 8 * f + 2 * q4;
            sacc[f][0] = 8.f * fmaf(ga0,  U[c0 * 132 + r0],       Ms[c0]);
            sacc[f][1] = 8.f * fmaf(ga0,  U[(c0 + 1) * 132 + r0], Ms[c0 + 1]);
            sacc[f][2] = 8.f * fmaf(ga1v, U[c0 * 132 + r1],       Ms[c0]);
            sacc[f][3] = 8.f * fmaf(ga1v, U[(c0 + 1) * 132 + r1], Ms[c0 + 1]);
        }
#pragma unroll
        for (int s = 0; s < 8; s++) {
            uint32_t bf[4][2];
#pragma unroll
            for (int f = 0; f < 4; f++) {
                bf[f][0] = Ks[8 * f + g][q4 + 8 * s];
                bf[f][1] = Ks[8 * f + g][q4 + 4 + 8 * s];
            }
#pragma unroll
            for (int f = 0; f < 4; f++) mma_tf32(sacc[f], qf[s], bf[f]);
        }
#pragma unroll
        for (int f = 0; f < 4; f++)
#pragma unroll
            for (int e = 0; e < 4; e++) sacc[f][e] *= 0.125f;

        __syncthreads();   // all RB reads done before P overwrites U

        // ---- online softmax ----
        float mt0 = sacc[0][0], mt1 = sacc[0][2];
#pragma unroll
        for (int f = 0; f < 4; f++) {
            mt0 = fmaxf(mt0, fmaxf(sacc[f][0], sacc[f][1]));
            mt1 = fmaxf(mt1, fmaxf(sacc[f][2], sacc[f][3]));
        }
        mt0 = fmaxf(mt0, __shfl_xor_sync(0xffffffffu, mt0, 1));
        mt0 = fmaxf(mt0, __shfl_xor_sync(0xffffffffu, mt0, 2));
        mt1 = fmaxf(mt1, __shfl_xor_sync(0xffffffffu, mt1, 1));
        mt1 = fmaxf(mt1, __shfl_xor_sync(0xffffffffu, mt1, 2));

        float mn0 = fmaxf(m_[0], mt0), mn1 = fmaxf(m_[1], mt1);
        float al0 = __expf(m_[0] - mn0), al1 = __expf(m_[1] - mn1);
        m_[0] = mn0; m_[1] = mn1;

        float ls0 = 0.f, ls1 = 0.f;
#pragma unroll
        for (int f = 0; f < 4; f++) {
            sacc[f][0] = __expf(sacc[f][0] - mn0);
            sacc[f][1] = __expf(sacc[f][1] - mn0);
            sacc[f][2] = __expf(sacc[f][2] - mn1);
            sacc[f][3] = __expf(sacc[f][3] - mn1);
            ls0 += sacc[f][0] + sacc[f][1];
            ls1 += sacc[f][2] + sacc[f][3];
        }
        ls0 += __shfl_xor_sync(0xffffffffu, ls0, 1);
        ls0 += __shfl_xor_sync(0xffffffffu, ls0, 2);
        ls1 += __shfl_xor_sync(0xffffffffu, ls1, 1);
        ls1 += __shfl_xor_sync(0xffffffffu, ls1, 2);
        l_[0] = l_[0] * al0 + ls0;
        l_[1] = l_[1] * al1 + ls1;
#pragma unroll
        for (int f = 0; f < 8; f++) {
            oacc[f][0] *= al0; oacc[f][1] *= al0;
            oacc[f][2] *= al1; oacc[f][3] *= al1;
        }

        // ---- stage P (tf32) ----
#pragma unroll
        for (int f = 0; f < 4; f++) {
            int c0 = 8 * f + 2 * q4;
            Pp[r0 * 36 + c0]     = f2tf(sacc[f][0]);
            Pp[r0 * 36 + c0 + 1] = f2tf(sacc[f][1]);
            Pp[r1 * 36 + c0]     = f2tf(sacc[f][2]);
            Pp[r1 * 36 + c0 + 1] = f2tf(sacc[f][3]);
        }
        __syncwarp();

        // ---- O += P @ V ----
#pragma unroll
        for (int s = 0; s < 4; s++) {
            uint32_t pa[4];
            pa[0] = Pp[r0 * 36 + q4 + 8 * s];
            pa[1] = Pp[r1 * 36 + q4 + 8 * s];
            pa[2] = Pp[r0 * 36 + q4 + 4 + 8 * s];
            pa[3] = Pp[r1 * 36 + q4 + 4 + 8 * s];
#pragma unroll
            for (int f = 0; f < 8; f++) {
                uint32_t vb[2];
                vb[0] = Vs[8 * s + q4][8 * f + g];
                vb[1] = Vs[8 * s + q4 + 4][8 * f + g];
                mma_tf32(oacc[f], pa, vb);
            }
        }
        __syncthreads();
    }

    // ---- finalize: O /= l ; write hi/lo split, row-major [b*t][h*64+hd] ----
    float inv0 = 1.f / l_[0], inv1 = 1.f / l_[1];
#pragma unroll
    for (int f = 0; f < 8; f++) {
        int c = 8 * f + 2 * q4;
        size_t i0 = ((size_t)b * T_ + q0 + r0) * D_ + h * HD_ + c;
        size_t i1 = ((size_t)b * T_ + q0 + r1) * D_ + h * HD_ + c;
        float v00 = oacc[f][0] * inv0, v01 = oacc[f][1] * inv0;
        float v10 = oacc[f][2] * inv1, v11 = oacc[f][3] * inv1;
        uint2 h0, h1, l0, l1;
        h0.x = f2tf(v00); l0.x = f2tf(v00 - __uint_as_float(h0.x));
        h0.y = f2tf(v01); l0.y = f2tf(v01 - __uint_as_float(h0.y));
        h1.x = f2tf(v10); l1.x = f2tf(v10 - __uint_as_float(h1.x));
        h1.y = f2tf(v11); l1.y = f2tf(v11 - __uint_as_float(h1.y));
        *(uint2*)(g_ahi + i0) = h0; *(uint2*)(g_alo + i0) = l0;
        *(uint2*)(g_ahi + i1) = h1; *(uint2*)(g_alo + i1) = l1;
    }
}

// ============================================================
extern "C" void kernel_launch(void* const* d_in, const int* in_sizes, int n_in,
                              void* d_out, int out_size)
{
    const float* x         = (const float*)d_in[0];
    const float* attn_mask = (const float*)d_in[1];
    const float* rel_bias  = (const float*)d_in[2];
    const float* Wq = (const float*)d_in[3];
    const float* bq = (const float*)d_in[4];
    const float* Wk = (const float*)d_in[5];
    const float* bk = (const float*)d_in[6];
    const float* Wv = (const float*)d_in[7];
    const float* bv = (const float*)d_in[8];
    const float* Wo = (const float*)d_in[9];
    const float* bo = (const float*)d_in[10];
    const float* Wg = (const float*)d_in[11];
    const float* bg = (const float*)d_in[12];
    const float* grep_a = (const float*)d_in[13];
    float* out = (float*)d_out;

    uint32_t *xhi, *wqh, *wkh, *wvh, *woh, *wol, *q, *k, *v, *ahi, *alo;
    float *ga1;
    cudaGetSymbolAddress((void**)&xhi, g_xhi);
    cudaGetSymbolAddress((void**)&wqh, g_wqh);
    cudaGetSymbolAddress((void**)&wkh, g_wkh);
    cudaGetSymbolAddress((void**)&wvh, g_wvh);
    cudaGetSymbolAddress((void**)&woh, g_woh);
    cudaGetSymbolAddress((void**)&wol, g_wol);
    cudaGetSymbolAddress((void**)&q,   g_q);
    cudaGetSymbolAddress((void**)&k,   g_k);
    cudaGetSymbolAddress((void**)&v,   g_v);
    cudaGetSymbolAddress((void**)&ahi, g_ahi);
    cudaGetSymbolAddress((void**)&alo, g_alo);
    cudaGetSymbolAddress((void**)&ga1, g_ga1);

    const int nx4 = N_ * D_ / 4;       // 1572864
    const int nw4 = D_ * D_ / 4;       // 147456
    conv_hi<<<(nx4 + 255) / 256, 256>>>((const float4*)x,  (uint4*)xhi, nx4);
    conv_hi<<<(nw4 + 255) / 256, 256>>>((const float4*)Wq, (uint4*)wqh, nw4);
    conv_hi<<<(nw4 + 255) / 256, 256>>>((const float4*)Wk, (uint4*)wkh, nw4);
    conv_hi<<<(nw4 + 255) / 256, 256>>>((const float4*)Wv, (uint4*)wvh, nw4);
    conv_hilo<<<(nw4 + 255) / 256, 256>>>((const float4*)Wo, (uint4*)woh, (uint4*)wol, nw4);

    dim3 ggrid(N_ / 128, D_ / 128);   // (64, 6)
    gemm_s1<<<ggrid, 256>>>(xhi, wqh, bq, q);
    gemm_s1<<<ggrid, 256>>>(xhi, wkh, bk, k);
    gemm_s1<<<ggrid, 256>>>(xhi, wvh, bv, v);
    wg2_kernel<<<1, 64>>>(Wg, bg);
    gates_kernel<<<BH_ * T_ / 8, 256>>>(x, grep_a, ga1);
    attn_kernel<<<dim3(T_ / 128, BH_), 256>>>(rel_bias, attn_mask);
    gemm_s3<<<ggrid, 256>>>(ahi, alo, woh, wol, bo, out);
}

// round 4
// speedup vs baseline: 3.0030x; 1.1733x over previous
#include <cuda_runtime.h>
#include <math.h>
#include <stdint.h>

#define B_  8
#define T_  1024
#define D_  768
#define H_  12
#define HD_ 64
#define BH_ (B_*H_)   /* 96 */
#define N_  (B_*T_)   /* 8192 */

// ---- scratch (static device globals; no allocation) ----
__device__ uint32_t g_xhi[N_*D_];
__device__ uint32_t g_wqh[D_*D_];
__device__ uint32_t g_wkh[D_*D_];
__device__ uint32_t g_wvh[D_*D_];
__device__ uint32_t g_woh[D_*D_];
__device__ uint32_t g_wol[D_*D_];
__device__ uint32_t g_q[BH_*T_*HD_];   // tf32
__device__ uint32_t g_k[BH_*T_*HD_];   // tf32
__device__ uint32_t g_v[BH_*T_*HD_];   // tf32
__device__ uint32_t g_ahi[N_*D_];      // attn out (tf32)
__device__ float    g_ga1[BH_*T_];
__device__ float    g_wg2[HD_*2];
__device__ float    g_bg2[2];

// ---- helpers ----
__device__ __forceinline__ uint32_t f2tf(float f) {
    uint32_t u;
    asm("cvt.rna.tf32.f32 %0, %1;" : "=r"(u) : "f"(f));
    return u;
}
__device__ __forceinline__ void mma_tf32(float* d, const uint32_t* a, const uint32_t* b) {
    asm volatile(
        "mma.sync.aligned.m16n8k8.row.col.f32.tf32.tf32.f32 "
        "{%0,%1,%2,%3}, {%4,%5,%6,%7}, {%8,%9}, {%0,%1,%2,%3};\n"
        : "+f"(d[0]), "+f"(d[1]), "+f"(d[2]), "+f"(d[3])
        : "r"(a[0]), "r"(a[1]), "r"(a[2]), "r"(a[3]), "r"(b[0]), "r"(b[1]));
}
__device__ __forceinline__ uint32_t saddr(const void* p) {
    return (uint32_t)__cvta_generic_to_shared(p);
}
__device__ __forceinline__ void cp16(uint32_t s, const void* g) {
    asm volatile("cp.async.cg.shared.global [%0], [%1], 16;\n" :: "r"(s), "l"(g));
}
#define CP_COMMIT() asm volatile("cp.async.commit_group;\n")
#define CP_WAIT2()  asm volatile("cp.async.wait_group 2;\n")
#define CP_WAIT1()  asm volatile("cp.async.wait_group 1;\n")
#define CP_WAIT0()  asm volatile("cp.async.wait_group 0;\n")

// ============================================================
// Preconversion kernels (run once, tiny)
// ============================================================
__global__ void conv_hi(const float4* __restrict__ in, uint4* __restrict__ hi, int n4)
{
    int i = blockIdx.x * blockDim.x + threadIdx.x;
    if (i >= n4) return;
    float4 v = in[i];
    uint4 h;
    h.x = f2tf(v.x); h.y = f2tf(v.y); h.z = f2tf(v.z); h.w = f2tf(v.w);
    hi[i] = h;
}
__global__ void conv_hilo(const float4* __restrict__ in, uint4* __restrict__ hi,
                          uint4* __restrict__ lo, int n4)
{
    int i = blockIdx.x * blockDim.x + threadIdx.x;
    if (i >= n4) return;
    float4 v = in[i];
    uint4 h, l;
    h.x = f2tf(v.x); l.x = f2tf(v.x - __uint_as_float(h.x));
    h.y = f2tf(v.y); l.y = f2tf(v.y - __uint_as_float(h.y));
    h.z = f2tf(v.z); l.z = f2tf(v.z - __uint_as_float(h.z));
    h.w = f2tf(v.w); l.w = f2tf(v.w - __uint_as_float(h.w));
    hi[i] = h; lo[i] = l;
}

// ============================================================
// Merged QKV GEMM (pre-tf32): out_z = tf32(x@W_z + b_z), head layout.
// BM=128 BN=128 BK=16, 3-stage cp.async ring. grid.z selects Q/K/V.
// stage layout (u32): As[128][20] (2560) + Bs[16][136] (2176) = 4736
// ============================================================
#define QKV_STAGE 4736
__global__ __launch_bounds__(256, 2)
void gemm_qkv(const uint32_t* __restrict__ A,
              const uint32_t* __restrict__ W0, const uint32_t* __restrict__ W1,
              const uint32_t* __restrict__ W2,
              const float* __restrict__ bb0, const float* __restrict__ bb1,
              const float* __restrict__ bb2,
              uint32_t* __restrict__ o0, uint32_t* __restrict__ o1,
              uint32_t* __restrict__ o2)
{
    extern __shared__ uint32_t sm[];
    const int z = blockIdx.z;
    const uint32_t* W = (z == 0) ? W0 : (z == 1) ? W1 : W2;
    const float* bias = (z == 0) ? bb0 : (z == 1) ? bb1 : bb2;
    uint32_t* out     = (z == 0) ? o0 : (z == 1) ? o1 : o2;

    const int tid = threadIdx.x;
    const int w = tid >> 5, lane = tid & 31, g = lane >> 2, q4 = lane & 3;
    const int wm = (w & 1) * 64, wn = (w >> 1) * 32;
    const int row0 = blockIdx.x * 128, col0 = blockIdx.y * 128;

    float acc[4][4][4];
#pragma unroll
    for (int i = 0; i < 4; i++)
#pragma unroll
        for (int f = 0; f < 4; f++)
#pragma unroll
            for (int e = 0; e < 4; e++) acc[i][f][e] = 0.f;

#define QKV_STAGE_LOAD(s, k0) do {                                             \
    uint32_t* As_ = sm + (s) * QKV_STAGE;                                      \
    uint32_t* Bs_ = As_ + 2560;                                                \
    _Pragma("unroll")                                                          \
    for (int i = 0; i < 2; i++) {                                              \
        int idx = tid + i * 256;                                               \
        int m = idx >> 2, kc = (idx & 3) * 4;                                  \
        cp16(saddr(&As_[m * 20 + kc]), A + (size_t)(row0 + m) * D_ + (k0) + kc); \
        int kk = idx >> 5, n4 = (idx & 31) * 4;                                \
        cp16(saddr(&Bs_[kk * 136 + n4]), W + (size_t)((k0) + kk) * D_ + col0 + n4); \
    } } while (0)

    QKV_STAGE_LOAD(0, 0);  CP_COMMIT();
    QKV_STAGE_LOAD(1, 16); CP_COMMIT();
    QKV_STAGE_LOAD(2, 32); CP_COMMIT();

    int st = 0;
    for (int kb = 0; kb < 48; kb++) {
        if (kb + 2 < 48) CP_WAIT2(); else CP_WAIT0();
        __syncthreads();
        const uint32_t* As = sm + st * QKV_STAGE;
        const uint32_t* Bs = As + 2560;
#pragma unroll
        for (int s = 0; s < 2; s++) {
            int kc = 8 * s + q4;
            uint32_t af[4][4], bf2[4][2];
#pragma unroll
            for (int i = 0; i < 4; i++) {
                int r = wm + 16 * i + g;
                af[i][0] = As[r * 20 + kc];       af[i][1] = As[(r + 8) * 20 + kc];
                af[i][2] = As[r * 20 + kc + 4];   af[i][3] = As[(r + 8) * 20 + kc + 4];
            }
#pragma unroll
            for (int f = 0; f < 4; f++) {
                int n = wn + 8 * f + g;
                bf2[f][0] = Bs[kc * 136 + n];
                bf2[f][1] = Bs[(kc + 4) * 136 + n];
            }
#pragma unroll
            for (int i = 0; i < 4; i++)
#pragma unroll
                for (int f = 0; f < 4; f++) mma_tf32(acc[i][f], af[i], bf2[f]);
        }
        __syncthreads();
        if (kb + 3 < 48) { QKV_STAGE_LOAD(st, (kb + 3) * 16); CP_COMMIT(); }
        st++; if (st == 3) st = 0;
    }

    // epilogue: +bias, tf32, head layout [bh][t][hd]
#pragma unroll
    for (int i = 0; i < 4; i++)
#pragma unroll
        for (int f = 0; f < 4; f++) {
            int col = col0 + wn + 8 * f + 2 * q4;
            float b0 = bias[col], b1 = bias[col + 1];
            int hh = col >> 6, hd = col & 63;
#pragma unroll
            for (int half = 0; half < 2; half++) {
                int row = row0 + wm + 16 * i + g + 8 * half;
                int bb = row >> 10, tt = row & 1023;
                uint2 u;
                u.x = f2tf(acc[i][f][2 * half + 0] + b0);
                u.y = f2tf(acc[i][f][2 * half + 1] + b1);
                *(uint2*)(out + ((size_t)(bb * H_ + hh) * T_ + tt) * HD_ + hd) = u;
            }
        }
}

// ============================================================
// O-proj GEMM, 2-term: out = f32(Ahi@(Whi+Wlo) + bias), row-major.
// BM=128 BN=128 BK=16, 3-stage ring.
// stage (u32): As[128][20] (2560) + Bh[16][136] (2176) + Bl (2176) = 6912
// ============================================================
#define O_STAGE 6912
__global__ __launch_bounds__(256, 2)
void gemm_o(const uint32_t* __restrict__ A,
            const uint32_t* __restrict__ Whi, const uint32_t* __restrict__ Wlo,
            const float* __restrict__ bias, float* __restrict__ out)
{
    extern __shared__ uint32_t sm[];
    const int tid = threadIdx.x;
    const int w = tid >> 5, lane = tid & 31, g = lane >> 2, q4 = lane & 3;
    const int wm = (w & 1) * 64, wn = (w >> 1) * 32;
    const int row0 = blockIdx.x * 128, col0 = blockIdx.y * 128;

    float acc[4][4][4];
#pragma unroll
    for (int i = 0; i < 4; i++)
#pragma unroll
        for (int f = 0; f < 4; f++)
#pragma unroll
            for (int e = 0; e < 4; e++) acc[i][f][e] = 0.f;

#define O_STAGE_LOAD(s, k0) do {                                               \
    uint32_t* As_ = sm + (s) * O_STAGE;                                        \
    uint32_t* Bh_ = As_ + 2560;                                                \
    uint32_t* Bl_ = Bh_ + 2176;                                                \
    _Pragma("unroll")                                                          \
    for (int i = 0; i < 2; i++) {                                              \
        int idx = tid + i * 256;                                               \
        int m = idx >> 2, kc = (idx & 3) * 4;                                  \
        cp16(saddr(&As_[m * 20 + kc]), A + (size_t)(row0 + m) * D_ + (k0) + kc); \
        int kk = idx >> 5, n4 = (idx & 31) * 4;                                \
        cp16(saddr(&Bh_[kk * 136 + n4]), Whi + (size_t)((k0) + kk) * D_ + col0 + n4); \
        cp16(saddr(&Bl_[kk * 136 + n4]), Wlo + (size_t)((k0) + kk) * D_ + col0 + n4); \
    } } while (0)

    O_STAGE_LOAD(0, 0);  CP_COMMIT();
    O_STAGE_LOAD(1, 16); CP_COMMIT();
    O_STAGE_LOAD(2, 32); CP_COMMIT();

    int st = 0;
    for (int kb = 0; kb < 48; kb++) {
        if (kb + 2 < 48) CP_WAIT2(); else CP_WAIT0();
        __syncthreads();
        const uint32_t* As = sm + st * O_STAGE;
        const uint32_t* Bh = As + 2560;
        const uint32_t* Bl = Bh + 2176;
#pragma unroll
        for (int s = 0; s < 2; s++) {
            int kc = 8 * s + q4;
            uint32_t af[4][4], bh[4][2], bl[4][2];
#pragma unroll
            for (int i = 0; i < 4; i++) {
                int r = wm + 16 * i + g;
                af[i][0] = As[r * 20 + kc];       af[i][1] = As[(r + 8) * 20 + kc];
                af[i][2] = As[r * 20 + kc + 4];   af[i][3] = As[(r + 8) * 20 + kc + 4];
            }
#pragma unroll
            for (int f = 0; f < 4; f++) {
                int n = wn + 8 * f + g;
                bh[f][0] = Bh[kc * 136 + n]; bh[f][1] = Bh[(kc + 4) * 136 + n];
                bl[f][0] = Bl[kc * 136 + n]; bl[f][1] = Bl[(kc + 4) * 136 + n];
            }
#pragma unroll
            for (int i = 0; i < 4; i++)
#pragma unroll
                for (int f = 0; f < 4; f++) {
                    mma_tf32(acc[i][f], af[i], bh[f]);
                    mma_tf32(acc[i][f], af[i], bl[f]);
                }
        }
        __syncthreads();
        if (kb + 3 < 48) { O_STAGE_LOAD(st, (kb + 3) * 16); CP_COMMIT(); }
        st++; if (st == 3) st = 0;
    }

#pragma unroll
    for (int i = 0; i < 4; i++)
#pragma unroll
        for (int f = 0; f < 4; f++) {
            int col = col0 + wn + 8 * f + 2 * q4;
            float b0 = bias[col], b1 = bias[col + 1];
#pragma unroll
            for (int half = 0; half < 2; half++) {
                int row = row0 + wm + 16 * i + g + 8 * half;
                float2 v;
                v.x = acc[i][f][2 * half + 0] + b0;
                v.y = acc[i][f][2 * half + 1] + b1;
                *(float2*)(out + (size_t)row * D_ + col) = v;
            }
        }
}

// ============================================================
// Wg row-sums + gates
// ============================================================
__global__ void wg2_kernel(const float* __restrict__ Wg, const float* __restrict__ bg)
{
    int d = threadIdx.x;
    const float* wg = Wg + d * 8;
    g_wg2[d * 2 + 0] = wg[0] + wg[1] + wg[2] + wg[3];
    g_wg2[d * 2 + 1] = wg[4] + wg[5] + wg[6] + wg[7];
    if (d == 0) {
        g_bg2[0] = bg[0] + bg[1] + bg[2] + bg[3];
        g_bg2[1] = bg[4] + bg[5] + bg[6] + bg[7];
    }
}
__global__ __launch_bounds__(256)
void gates_kernel(const float* __restrict__ x, const float* __restrict__ grep_a,
                  float* __restrict__ ga1)
{
    int w    = blockIdx.x * 8 + (threadIdx.x >> 5);
    int lane = threadIdx.x & 31;
    int bh = w >> 10, t = w & 1023;
    int b = bh / H_, h = bh % H_;
    const float* xp = x + ((size_t)b * T_ + t) * D_ + h * HD_;

    float s0 = 0.f, s1 = 0.f;
#pragma unroll
    for (int d = lane; d < HD_; d += 32) {
        float xv = xp[d];
        s0 += xv * g_wg2[d * 2 + 0];
        s1 += xv * g_wg2[d * 2 + 1];
    }
#pragma unroll
    for (int off = 16; off > 0; off >>= 1) {
        s0 += __shfl_xor_sync(0xffffffffu, s0, off);
        s1 += __shfl_xor_sync(0xffffffffu, s1, off);
    }
    if (lane == 0) {
        s0 += g_bg2[0];
        s1 += g_bg2[1];
        float ga = 1.f / (1.f + expf(-s0));
        float gb = 1.f / (1.f + expf(-s1));
        ga1[w] = ga * (gb * grep_a[h] - 1.f) + 2.f;
    }
}

// ============================================================
// Flash attention, 2-stage pipelined staging (cp.async ring).
// q-tile 128, k-tile 32, 8 warps. q/k/v pre-tf32. Output hi-tf32 only.
// stage (floats): Ks[32][68]u (2176) + Vs[32][68]u (2176) + RB[32][132] (4224) = 8576
// + P[128][36]u (4608) + Ms[1024]   => 22784 floats = 91136 B dynamic
// ============================================================
#define ATT_STAGE 8576
__global__ __launch_bounds__(256, 2)
void attn_kernel(const float* __restrict__ rel_bias,
                 const float* __restrict__ attn_mask)
{
    extern __shared__ float smf[];
    uint32_t* Pp = (uint32_t*)(smf + 2 * ATT_STAGE);   // [128][36]
    float*    Ms = smf + 2 * ATT_STAGE + 4608;         // [1024]

    const int tid  = threadIdx.x;
    const int w    = tid >> 5;
    const int lane = tid & 31;
    const int g    = lane >> 2;
    const int q4   = lane & 3;
    const int qb   = 16 * w;
    const int q0   = blockIdx.x * 128;
    const int bh   = blockIdx.y;
    const int b    = bh / H_, h = bh % H_;

    const uint32_t* qptr = g_q + (size_t)bh * T_ * HD_;
    const uint32_t* kptr = g_k + (size_t)bh * T_ * HD_;
    const uint32_t* vptr = g_v + (size_t)bh * T_ * HD_;

    const int r0 = qb + g;
    const int r1 = qb + g + 8;

#define ATT_STAGE_LOAD(s, k0) do {                                             \
    uint32_t* Ks_ = (uint32_t*)(smf + (s) * ATT_STAGE);                        \
    uint32_t* Vs_ = Ks_ + 2176;                                                \
    float*    RB_ = smf + (s) * ATT_STAGE + 4352;                              \
    _Pragma("unroll")                                                          \
    for (int i = 0; i < 2; i++) {                                              \
        int idx = tid + i * 256;                                               \
        int kk = idx >> 4, d4 = (idx & 15) * 4;                                \
        cp16(saddr(&Ks_[kk * 68 + d4]), kptr + (size_t)((k0) + kk) * HD_ + d4);\
        cp16(saddr(&Vs_[kk * 68 + d4]), vptr + (size_t)((k0) + kk) * HD_ + d4);\
    }                                                                          \
    const float* rbp_ = rel_bias + ((size_t)bh * T_ + (k0)) * T_ + q0;         \
    _Pragma("unroll")                                                          \
    for (int i = 0; i < 4; i++) {                                              \
        int idx = tid + i * 256;                                               \
        int kk = idx >> 5, qq = (idx & 31) * 4;                                \
        cp16(saddr(&RB_[kk * 132 + qq]), rbp_ + (size_t)kk * T_ + qq);         \
    } } while (0)

    // prologue: stage 0 (+mask row), stage 1
    ATT_STAGE_LOAD(0, 0);
    cp16(saddr(&Ms[tid * 4]), attn_mask + (size_t)b * T_ + tid * 4);
    CP_COMMIT();
    ATT_STAGE_LOAD(1, 32);
    CP_COMMIT();

    // Q fragments (LDG overlaps the cp.asyncs above)
    uint32_t qf[8][4];
    {
        const uint32_t* qa = qptr + (size_t)(q0 + r0) * HD_;
        const uint32_t* qc = qptr + (size_t)(q0 + r1) * HD_;
#pragma unroll
        for (int s = 0; s < 8; s++) {
            qf[s][0] = qa[q4 + 8 * s];
            qf[s][1] = qc[q4 + 8 * s];
            qf[s][2] = qa[q4 + 4 + 8 * s];
            qf[s][3] = qc[q4 + 4 + 8 * s];
        }
    }
    const float ga0  = g_ga1[(size_t)bh * T_ + q0 + r0];
    const float ga1v = g_ga1[(size_t)bh * T_ + q0 + r1];

    float m_[2] = {-INFINITY, -INFINITY};
    float l_[2] = {0.f, 0.f};
    float oacc[8][4];
#pragma unroll
    for (int f = 0; f < 8; f++)
#pragma unroll
        for (int e = 0; e < 4; e++) oacc[f][e] = 0.f;

    for (int kt = 0; kt < 32; kt++) {
        if (kt + 1 < 32) CP_WAIT1(); else CP_WAIT0();
        __syncthreads();
        const int cur = kt & 1;
        const uint32_t* Ks = (const uint32_t*)(smf + cur * ATT_STAGE);
        const uint32_t* Vs = Ks + 2176;
        const float*    RB = smf + cur * ATT_STAGE + 4352;
        const int k0 = kt * 32;

        // ---- S = 8*(ga*rb + mask) init, += Q.K, *0.125 ----
        float sacc[4][4];
#pragma unroll
        for (int f = 0; f < 4; f++) {
            int c0 = 8 * f + 2 * q4;
            sacc[f][0] = 8.f * fmaf(ga0,  RB[c0 * 132 + r0],       Ms[k0 + c0]);
            sacc[f][1] = 8.f * fmaf(ga0,  RB[(c0 + 1) * 132 + r0], Ms[k0 + c0 + 1]);
            sacc[f][2] = 8.f * fmaf(ga1v, RB[c0 * 132 + r1],       Ms[k0 + c0]);
            sacc[f][3] = 8.f * fmaf(ga1v, RB[(c0 + 1) * 132 + r1], Ms[k0 + c0 + 1]);
        }
#pragma unroll
        for (int s = 0; s < 8; s++) {
            uint32_t bf[4][2];
#pragma unroll
            for (int f = 0; f < 4; f++) {
                bf[f][0] = Ks[(8 * f + g) * 68 + q4 + 8 * s];
                bf[f][1] = Ks[(8 * f + g) * 68 + q4 + 4 + 8 * s];
            }
#pragma unroll
            for (int f = 0; f < 4; f++) mma_tf32(sacc[f], qf[s], bf[f]);
        }
#pragma unroll
        for (int f = 0; f < 4; f++)
#pragma unroll
            for (int e = 0; e < 4; e++) sacc[f][e] *= 0.125f;

        // ---- online softmax ----
        float mt0 = sacc[0][0], mt1 = sacc[0][2];
#pragma unroll
        for (int f = 0; f < 4; f++) {
            mt0 = fmaxf(mt0, fmaxf(sacc[f][0], sacc[f][1]));
            mt1 = fmaxf(mt1, fmaxf(sacc[f][2], sacc[f][3]));
        }
        mt0 = fmaxf(mt0, __shfl_xor_sync(0xffffffffu, mt0, 1));
        mt0 = fmaxf(mt0, __shfl_xor_sync(0xffffffffu, mt0, 2));
        mt1 = fmaxf(mt1, __shfl_xor_sync(0xffffffffu, mt1, 1));
        mt1 = fmaxf(mt1, __shfl_xor_sync(0xffffffffu, mt1, 2));

        float mn0 = fmaxf(m_[0], mt0), mn1 = fmaxf(m_[1], mt1);
        float al0 = __expf(m_[0] - mn0), al1 = __expf(m_[1] - mn1);
        m_[0] = mn0; m_[1] = mn1;

        float ls0 = 0.f, ls1 = 0.f;
#pragma unroll
        for (int f = 0; f < 4; f++) {
            sacc[f][0] = __expf(sacc[f][0] - mn0);
            sacc[f][1] = __expf(sacc[f][1] - mn0);
            sacc[f][2] = __expf(sacc[f][2] - mn1);
            sacc[f][3] = __expf(sacc[f][3] - mn1);
            ls0 += sacc[f][0] + sacc[f][1];
            ls1 += sacc[f][2] + sacc[f][3];
        }
        ls0 += __shfl_xor_sync(0xffffffffu, ls0, 1);
        ls0 += __shfl_xor_sync(0xffffffffu, ls0, 2);
        ls1 += __shfl_xor_sync(0xffffffffu, ls1, 1);
        ls1 += __shfl_xor_sync(0xffffffffu, ls1, 2);
        l_[0] = l_[0] * al0 + ls0;
        l_[1] = l_[1] * al1 + ls1;
#pragma unroll
        for (int f = 0; f < 8; f++) {
            oacc[f][0] *= al0; oacc[f][1] *= al0;
            oacc[f][2] *= al1; oacc[f][3] *= al1;
        }

        // ---- stage P (tf32) into warp-private rows ----
#pragma unroll
        for (int f = 0; f < 4; f++) {
            int c0 = 8 * f + 2 * q4;
            Pp[r0 * 36 + c0]     = f2tf(sacc[f][0]);
            Pp[r0 * 36 + c0 + 1] = f2tf(sacc[f][1]);
            Pp[r1 * 36 + c0]     = f2tf(sacc[f][2]);
            Pp[r1 * 36 + c0 + 1] = f2tf(sacc[f][3]);
        }
        __syncwarp();

        // ---- O += P @ V ----
#pragma unroll
        for (int s = 0; s < 4; s++) {
            uint32_t pa[4];
            pa[0] = Pp[r0 * 36 + q4 + 8 * s];
            pa[1] = Pp[r1 * 36 + q4 + 8 * s];
            pa[2] = Pp[r0 * 36 + q4 + 4 + 8 * s];
            pa[3] = Pp[r1 * 36 + q4 + 4 + 8 * s];
#pragma unroll
            for (int f = 0; f < 8; f++) {
                uint32_t vb[2];
                vb[0] = Vs[(8 * s + q4) * 68 + 8 * f + g];
                vb[1] = Vs[(8 * s + q4 + 4) * 68 + 8 * f + g];
                mma_tf32(oacc[f], pa, vb);
            }
        }
        __syncthreads();   // all warps done with buffer `cur`
        if (kt + 2 < 32) { ATT_STAGE_LOAD(cur, (kt + 2) * 32); CP_COMMIT(); }
    }

    // ---- finalize: O /= l ; write hi tf32, row-major [b*t][h*64+hd] ----
    float inv0 = 1.f / l_[0], inv1 = 1.f / l_[1];
#pragma unroll
    for (int f = 0; f < 8; f++) {
        int c = 8 * f + 2 * q4;
        size_t i0 = ((size_t)b * T_ + q0 + r0) * D_ + h * HD_ + c;
        size_t i1 = ((size_t)b * T_ + q0 + r1) * D_ + h * HD_ + c;
        uint2 h0, h1;
        h0.x = f2tf(oacc[f][0] * inv0); h0.y = f2tf(oacc[f][1] * inv0);
        h1.x = f2tf(oacc[f][2] * inv1); h1.y = f2tf(oacc[f][3] * inv1);
        *(uint2*)(g_ahi + i0) = h0;
        *(uint2*)(g_ahi + i1) = h1;
    }
}

// ============================================================
extern "C" void kernel_launch(void* const* d_in, const int* in_sizes, int n_in,
                              void* d_out, int out_size)
{
    const float* x         = (const float*)d_in[0];
    const float* attn_mask = (const float*)d_in[1];
    const float* rel_bias  = (const float*)d_in[2];
    const float* Wq = (const float*)d_in[3];
    const float* bq = (const float*)d_in[4];
    const float* Wk = (const float*)d_in[5];
    const float* bk = (const float*)d_in[6];
    const float* Wv = (const float*)d_in[7];
    const float* bv = (const float*)d_in[8];
    const float* Wo = (const float*)d_in[9];
    const float* bo = (const float*)d_in[10];
    const float* Wg = (const float*)d_in[11];
    const float* bg = (const float*)d_in[12];
    const float* grep_a = (const float*)d_in[13];
    float* out = (float*)d_out;

    uint32_t *xhi, *wqh, *wkh, *wvh, *woh, *wol, *q, *k, *v, *ahi;
    float *ga1;
    cudaGetSymbolAddress((void**)&xhi, g_xhi);
    cudaGetSymbolAddress((void**)&wqh, g_wqh);
    cudaGetSymbolAddress((void**)&wkh, g_wkh);
    cudaGetSymbolAddress((void**)&wvh, g_wvh);
    cudaGetSymbolAddress((void**)&woh, g_woh);
    cudaGetSymbolAddress((void**)&wol, g_wol);
    cudaGetSymbolAddress((void**)&q,   g_q);
    cudaGetSymbolAddress((void**)&k,   g_k);
    cudaGetSymbolAddress((void**)&v,   g_v);
    cudaGetSymbolAddress((void**)&ahi, g_ahi);
    cudaGetSymbolAddress((void**)&ga1, g_ga1);

    // idempotent; host-side, no allocation
    cudaFuncSetAttribute(gemm_qkv,  cudaFuncAttributeMaxDynamicSharedMemorySize, QKV_STAGE * 3 * 4);
    cudaFuncSetAttribute(gemm_o,    cudaFuncAttributeMaxDynamicSharedMemorySize, O_STAGE * 3 * 4);
    cudaFuncSetAttribute(attn_kernel, cudaFuncAttributeMaxDynamicSharedMemorySize, 91136);

    const int nx4 = N_ * D_ / 4;
    const int nw4 = D_ * D_ / 4;
    conv_hi<<<(nx4 + 255) / 256, 256>>>((const float4*)x,  (uint4*)xhi, nx4);
    conv_hi<<<(nw4 + 255) / 256, 256>>>((const float4*)Wq, (uint4*)wqh, nw4);
    conv_hi<<<(nw4 + 255) / 256, 256>>>((const float4*)Wk, (uint4*)wkh, nw4);
    conv_hi<<<(nw4 + 255) / 256, 256>>>((const float4*)Wv, (uint4*)wvh, nw4);
    conv_hilo<<<(nw4 + 255) / 256, 256>>>((const float4*)Wo, (uint4*)woh, (uint4*)wol, nw4);

    wg2_kernel<<<1, 64>>>(Wg, bg);
    gates_kernel<<<BH_ * T_ / 8, 256>>>(x, grep_a, ga1);

    gemm_qkv<<<dim3(N_ / 128, D_ / 128, 3), 256, QKV_STAGE * 3 * 4>>>(
        xhi, wqh, wkh, wvh, bq, bk, bv, q, k, v);

    attn_kernel<<<dim3(T_ / 128, BH_), 256, 91136>>>(rel_bias, attn_mask);

    gemm_o<<<dim3(N_ / 128, D_ / 128), 256, O_STAGE * 3 * 4>>>(ahi, woh, wol, bo, out);
}

// round 6
// speedup vs baseline: 3.0783x; 1.0251x over previous
#include <cuda_runtime.h>
#include <cuda_bf16.h>
#include <math.h>
#include <stdint.h>

#define B_  8
#define T_  1024
#define D_  768
#define H_  12
#define HD_ 64
#define BH_ (B_*H_)   /* 96 */
#define N_  (B_*T_)   /* 8192 */

// ---- scratch (static device globals; no allocation) ----
__device__ uint32_t g_xhi[N_*D_];          // x as tf32
__device__ uint32_t g_wqh[D_*D_];          // Wq tf32
__device__ uint32_t g_wkh[D_*D_];
__device__ uint32_t g_wvh[D_*D_];
__device__ __nv_bfloat16 g_woth[D_*D_];    // Wo^T bf16 hi  [n][k]
__device__ __nv_bfloat16 g_wotl[D_*D_];    // Wo^T bf16 lo
__device__ uint32_t g_q[BH_*T_*HD_];       // tf32, head layout
__device__ uint32_t g_k[BH_*T_*HD_];
__device__ uint32_t g_v[BH_*T_*HD_];
__device__ __nv_bfloat16 g_oh[N_*D_];      // attn out hi bf16, row-major
__device__ __nv_bfloat16 g_ol[N_*D_];      // attn out lo
__device__ float    g_ga1[BH_*T_];
__device__ float    g_wg2[HD_*2];
__device__ float    g_bg2[2];

// ---- helpers ----
__device__ __forceinline__ uint32_t f2tf(float f) {
    uint32_t u;
    asm("cvt.rna.tf32.f32 %0, %1;" : "=r"(u) : "f"(f));
    return u;
}
__device__ __forceinline__ void mma_tf32(float* d, const uint32_t* a, const uint32_t* b) {
    asm volatile(
        "mma.sync.aligned.m16n8k8.row.col.f32.tf32.tf32.f32 "
        "{%0,%1,%2,%3}, {%4,%5,%6,%7}, {%8,%9}, {%0,%1,%2,%3};\n"
        : "+f"(d[0]), "+f"(d[1]), "+f"(d[2]), "+f"(d[3])
        : "r"(a[0]), "r"(a[1]), "r"(a[2]), "r"(a[3]), "r"(b[0]), "r"(b[1]));
}
__device__ __forceinline__ void mma_bf16(float* d, const uint32_t* a, const uint32_t* b) {
    asm volatile(
        "mma.sync.aligned.m16n8k16.row.col.f32.bf16.bf16.f32 "
        "{%0,%1,%2,%3}, {%4,%5,%6,%7}, {%8,%9}, {%0,%1,%2,%3};\n"
        : "+f"(d[0]), "+f"(d[1]), "+f"(d[2]), "+f"(d[3])
        : "r"(a[0]), "r"(a[1]), "r"(a[2]), "r"(a[3]), "r"(b[0]), "r"(b[1]));
}
#define LDSM_X4(r, a) \
    asm volatile("ldmatrix.sync.aligned.m8n8.x4.shared.b16 {%0,%1,%2,%3}, [%4];" \
        : "=r"((r)[0]), "=r"((r)[1]), "=r"((r)[2]), "=r"((r)[3]) : "r"(a))

__device__ __forceinline__ uint32_t saddr(const void* p) {
    return (uint32_t)__cvta_generic_to_shared(p);
}
__device__ __forceinline__ void cp16(uint32_t s, const void* g) {
    asm volatile("cp.async.cg.shared.global [%0], [%1], 16;\n" :: "r"(s), "l"(g));
}
#define CP_COMMIT() asm volatile("cp.async.commit_group;\n")
#define CP_WAIT2()  asm volatile("cp.async.wait_group 2;\n")
#define CP_WAIT1()  asm volatile("cp.async.wait_group 1;\n")
#define CP_WAIT0()  asm volatile("cp.async.wait_group 0;\n")

__device__ __forceinline__ void bfsplit(float f, __nv_bfloat16& h, __nv_bfloat16& l) {
    h = __float2bfloat16(f);
    l = __float2bfloat16(f - __bfloat162float(h));
}

// ============================================================
// conv_x: x -> tf32 u32 (+ block 0 computes Wg row-sums)
// ============================================================
__global__ void conv_x(const float4* __restrict__ in, uint4* __restrict__ hi, int n4,
                       const float* __restrict__ Wg, const float* __restrict__ bg)
{
    int i = blockIdx.x * blockDim.x + threadIdx.x;
    if (blockIdx.x == 0 && threadIdx.x < 64) {
        int d = threadIdx.x;
        const float* wg = Wg + d * 8;
        g_wg2[d * 2 + 0] = wg[0] + wg[1] + wg[2] + wg[3];
        g_wg2[d * 2 + 1] = wg[4] + wg[5] + wg[6] + wg[7];
        if (d == 0) {
            g_bg2[0] = bg[0] + bg[1] + bg[2] + bg[3];
            g_bg2[1] = bg[4] + bg[5] + bg[6] + bg[7];
        }
    }
    if (i >= n4) return;
    float4 v = in[i];
    uint4 h;
    h.x = f2tf(v.x); h.y = f2tf(v.y); h.z = f2tf(v.z); h.w = f2tf(v.w);
    hi[i] = h;
}

// ============================================================
// conv_w3: Wq/Wk/Wv -> tf32 u32 (grid.z)
// ============================================================
__global__ void conv_w3(const float4* __restrict__ W0, const float4* __restrict__ W1,
                        const float4* __restrict__ W2,
                        uint4* __restrict__ o0, uint4* __restrict__ o1,
                        uint4* __restrict__ o2, int n4)
{
    int i = blockIdx.x * blockDim.x + threadIdx.x;
    if (i >= n4) return;
    const float4* in = (blockIdx.z == 0) ? W0 : (blockIdx.z == 1) ? W1 : W2;
    uint4* out = (blockIdx.z == 0) ? o0 : (blockIdx.z == 1) ? o1 : o2;
    float4 v = in[i];
    uint4 h;
    h.x = f2tf(v.x); h.y = f2tf(v.y); h.z = f2tf(v.z); h.w = f2tf(v.w);
    out[i] = h;
}

// ============================================================
// conv_woT: Wo -> Wo^T bf16 hi/lo  ([n][k], k contiguous)
// ============================================================
__global__ void conv_woT(const float* __restrict__ W,
                         __nv_bfloat16* __restrict__ th, __nv_bfloat16* __restrict__ tl)
{
    __shared__ float tile[32][33];
    int n0 = blockIdx.x * 32, k0 = blockIdx.y * 32;
    int tx = threadIdx.x, ty = threadIdx.y;
    tile[ty][tx] = W[(size_t)(k0 + ty) * D_ + n0 + tx];
    __syncthreads();
    float f = tile[tx][ty];
    __nv_bfloat16 h, l;
    bfsplit(f, h, l);
    size_t o = (size_t)(n0 + ty) * D_ + k0 + tx;
    th[o] = h; tl[o] = l;
}

// ============================================================
// Gates: warp per (bh,t) using precomputed wg2.
// ============================================================
__global__ __launch_bounds__(256)
void gates_kernel(const float* __restrict__ x, const float* __restrict__ grep_a,
                  float* __restrict__ ga1)
{
    int w    = blockIdx.x * 8 + (threadIdx.x >> 5);
    int lane = threadIdx.x & 31;
    int bh = w >> 10, t = w & 1023;
    int b = bh / H_, h = bh % H_;
    const float* xp = x + ((size_t)b * T_ + t) * D_ + h * HD_;

    float s0 = 0.f, s1 = 0.f;
#pragma unroll
    for (int d = lane; d < HD_; d += 32) {
        float xv = xp[d];
        s0 += xv * g_wg2[d * 2 + 0];
        s1 += xv * g_wg2[d * 2 + 1];
    }
#pragma unroll
    for (int off = 16; off > 0; off >>= 1) {
        s0 += __shfl_xor_sync(0xffffffffu, s0, off);
        s1 += __shfl_xor_sync(0xffffffffu, s1, off);
    }
    if (lane == 0) {
        s0 += g_bg2[0];
        s1 += g_bg2[1];
        float ga = 1.f / (1.f + expf(-s0));
        float gb = 1.f / (1.f + expf(-s1));
        ga1[w] = ga * (gb * grep_a[h] - 1.f) + 2.f;
    }
}

// ============================================================
// Merged QKV GEMM (tf32, 1-term): out_z = tf32(x@W_z + b_z), head layout.
// BM=128 BN=128 BK=16, 3-stage cp.async ring. (R3 kernel, unchanged)
// ============================================================
#define QKV_STAGE 4736
__global__ __launch_bounds__(256, 2)
void gemm_qkv(const uint32_t* __restrict__ A,
              const uint32_t* __restrict__ W0, const uint32_t* __restrict__ W1,
              const uint32_t* __restrict__ W2,
              const float* __restrict__ bb0, const float* __restrict__ bb1,
              const float* __restrict__ bb2,
              uint32_t* __restrict__ o0, uint32_t* __restrict__ o1,
              uint32_t* __restrict__ o2)
{
    extern __shared__ uint32_t sm[];
    const int z = blockIdx.z;
    const uint32_t* W = (z == 0) ? W0 : (z == 1) ? W1 : W2;
    const float* bias = (z == 0) ? bb0 : (z == 1) ? bb1 : bb2;
    uint32_t* out     = (z == 0) ? o0 : (z == 1) ? o1 : o2;

    const int tid = threadIdx.x;
    const int w = tid >> 5, lane = tid & 31, g = lane >> 2, q4 = lane & 3;
    const int wm = (w & 1) * 64, wn = (w >> 1) * 32;
    const int row0 = blockIdx.x * 128, col0 = blockIdx.y * 128;

    float acc[4][4][4];
#pragma unroll
    for (int i = 0; i < 4; i++)
#pragma unroll
        for (int f = 0; f < 4; f++)
#pragma unroll
            for (int e = 0; e < 4; e++) acc[i][f][e] = 0.f;

#define QKV_STAGE_LOAD(s, k0) do {                                             \
    uint32_t* As_ = sm + (s) * QKV_STAGE;                                      \
    uint32_t* Bs_ = As_ + 2560;                                                \
    _Pragma("unroll")                                                          \
    for (int i = 0; i < 2; i++) {                                              \
        int idx = tid + i * 256;                                               \
        int m = idx >> 2, kc = (idx & 3) * 4;                                  \
        cp16(saddr(&As_[m * 20 + kc]), A + (size_t)(row0 + m) * D_ + (k0) + kc); \
        int kk = idx >> 5, n4 = (idx & 31) * 4;                                \
        cp16(saddr(&Bs_[kk * 136 + n4]), W + (size_t)((k0) + kk) * D_ + col0 + n4); \
    } } while (0)

    QKV_STAGE_LOAD(0, 0);  CP_COMMIT();
    QKV_STAGE_LOAD(1, 16); CP_COMMIT();
    QKV_STAGE_LOAD(2, 32); CP_COMMIT();

    int st = 0;
    for (int kb = 0; kb < 48; kb++) {
        if (kb + 2 < 48) CP_WAIT2(); else CP_WAIT0();
        __syncthreads();
        const uint32_t* As = sm + st * QKV_STAGE;
        const uint32_t* Bs = As + 2560;
#pragma unroll
        for (int s = 0; s < 2; s++) {
            int kc = 8 * s + q4;
            uint32_t af[4][4], bf2[4][2];
#pragma unroll
            for (int i = 0; i < 4; i++) {
                int r = wm + 16 * i + g;
                af[i][0] = As[r * 20 + kc];       af[i][1] = As[(r + 8) * 20 + kc];
                af[i][2] = As[r * 20 + kc + 4];   af[i][3] = As[(r + 8) * 20 + kc + 4];
            }
#pragma unroll
            for (int f = 0; f < 4; f++) {
                int n = wn + 8 * f + g;
                bf2[f][0] = Bs[kc * 136 + n];
                bf2[f][1] = Bs[(kc + 4) * 136 + n];
            }
#pragma unroll
            for (int i = 0; i < 4; i++)
#pragma unroll
                for (int f = 0; f < 4; f++) mma_tf32(acc[i][f], af[i], bf2[f]);
        }
        __syncthreads();
        if (kb + 3 < 48) { QKV_STAGE_LOAD(st, (kb + 3) * 16); CP_COMMIT(); }
        st++; if (st == 3) st = 0;
    }

#pragma unroll
    for (int i = 0; i < 4; i++)
#pragma unroll
        for (int f = 0; f < 4; f++) {
            int col = col0 + wn + 8 * f + 2 * q4;
            float b0 = bias[col], b1 = bias[col + 1];
            int hh = col >> 6, hd = col & 63;
#pragma unroll
            for (int half = 0; half < 2; half++) {
                int row = row0 + wm + 16 * i + g + 8 * half;
                int bb = row >> 10, tt = row & 1023;
                uint2 u;
                u.x = f2tf(acc[i][f][2 * half + 0] + b0);
                u.y = f2tf(acc[i][f][2 * half + 1] + b1);
                *(uint2*)(out + ((size_t)(bb * H_ + hh) * T_ + tt) * HD_ + hd) = u;
            }
        }
}

// ============================================================
// Flash attention (R3 core), softmax in exp2 domain, bf16 hi/lo epilogue.
// ============================================================
#define ATT_STAGE 8576
#define C_SM (0.125f * 1.44269504088896340736f)   /* 0.125*log2(e) */
__global__ __launch_bounds__(256, 2)
void attn_kernel(const float* __restrict__ rel_bias,
                 const float* __restrict__ attn_mask)
{
    extern __shared__ float smf[];
    uint32_t* Pp = (uint32_t*)(smf + 2 * ATT_STAGE);   // [128][36]
    float*    Ms = smf + 2 * ATT_STAGE + 4608;         // [1024]

    const int tid  = threadIdx.x;
    const int w    = tid >> 5;
    const int lane = tid & 31;
    const int g    = lane >> 2;
    const int q4   = lane & 3;
    const int qb   = 16 * w;
    const int q0   = blockIdx.x * 128;
    const int bh   = blockIdx.y;
    const int b    = bh / H_, h = bh % H_;

    const uint32_t* qptr = g_q + (size_t)bh * T_ * HD_;
    const uint32_t* kptr = g_k + (size_t)bh * T_ * HD_;
    const uint32_t* vptr = g_v + (size_t)bh * T_ * HD_;

    const int r0 = qb + g;
    const int r1 = qb + g + 8;

#define ATT_STAGE_LOAD(s, k0) do {                                             \
    uint32_t* Ks_ = (uint32_t*)(smf + (s) * ATT_STAGE);                        \
    uint32_t* Vs_ = Ks_ + 2176;                                                \
    float*    RB_ = smf + (s) * ATT_STAGE + 4352;                              \
    _Pragma("unroll")                                                          \
    for (int i = 0; i < 2; i++) {                                              \
        int idx = tid + i * 256;                                               \
        int kk = idx >> 4, d4 = (idx & 15) * 4;                                \
        cp16(saddr(&Ks_[kk * 68 + d4]), kptr + (size_t)((k0) + kk) * HD_ + d4);\
        cp16(saddr(&Vs_[kk * 68 + d4]), vptr + (size_t)((k0) + kk) * HD_ + d4);\
    }                                                                          \
    const float* rbp_ = rel_bias + ((size_t)bh * T_ + (k0)) * T_ + q0;         \
    _Pragma("unroll")                                                          \
    for (int i = 0; i < 4; i++) {                                              \
        int idx = tid + i * 256;                                               \
        int kk = idx >> 5, qq = (idx & 31) * 4;                                \
        cp16(saddr(&RB_[kk * 132 + qq]), rbp_ + (size_t)kk * T_ + qq);         \
    } } while (0)

    ATT_STAGE_LOAD(0, 0);
    cp16(saddr(&Ms[tid * 4]), attn_mask + (size_t)b * T_ + tid * 4);
    CP_COMMIT();
    ATT_STAGE_LOAD(1, 32);
    CP_COMMIT();

    uint32_t qf[8][4];
    {
        const uint32_t* qa = qptr + (size_t)(q0 + r0) * HD_;
        const uint32_t* qc = qptr + (size_t)(q0 + r1) * HD_;
#pragma unroll
        for (int s = 0; s < 8; s++) {
            qf[s][0] = qa[q4 + 8 * s];
            qf[s][1] = qc[q4 + 8 * s];
            qf[s][2] = qa[q4 + 4 + 8 * s];
            qf[s][3] = qc[q4 + 4 + 8 * s];
        }
    }
    const float ga0  = g_ga1[(size_t)bh * T_ + q0 + r0];
    const float ga1v = g_ga1[(size_t)bh * T_ + q0 + r1];

    float m_[2] = {-INFINITY, -INFINITY};
    float l_[2] = {0.f, 0.f};
    float oacc[8][4];
#pragma unroll
    for (int f = 0; f < 8; f++)
#pragma unroll
        for (int e = 0; e < 4; e++) oacc[f][e] = 0.f;

    for (int kt = 0; kt < 32; kt++) {
        if (kt + 1 < 32) CP_WAIT1(); else CP_WAIT0();
        __syncthreads();
        const int cur = kt & 1;
        const uint32_t* Ks = (const uint32_t*)(smf + cur * ATT_STAGE);
        const uint32_t* Vs = Ks + 2176;
        const float*    RB = smf + cur * ATT_STAGE + 4352;
        const int k0 = kt * 32;

        // ---- S_raw = 8*(ga*rb + mask) + Q.K ; log2 domain: S_raw * C_SM ----
        float sacc[4][4];
#pragma unroll
        for (int f = 0; f < 4; f++) {
            int c0 = 8 * f + 2 * q4;
            sacc[f][0] = 8.f * fmaf(ga0,  RB[c0 * 132 + r0],       Ms[k0 + c0]);
            sacc[f][1] = 8.f * fmaf(ga0,  RB[(c0 + 1) * 132 + r0], Ms[k0 + c0 + 1]);
            sacc[f][2] = 8.f * fmaf(ga1v, RB[c0 * 132 + r1],       Ms[k0 + c0]);
            sacc[f][3] = 8.f * fmaf(ga1v, RB[(c0 + 1) * 132 + r1], Ms[k0 + c0 + 1]);
        }
#pragma unroll
        for (int s = 0; s < 8; s++) {
            uint32_t bf[4][2];
#pragma unroll
            for (int f = 0; f < 4; f++) {
                bf[f][0] = Ks[(8 * f + g) * 68 + q4 + 8 * s];
                bf[f][1] = Ks[(8 * f + g) * 68 + q4 + 4 + 8 * s];
            }
#pragma unroll
            for (int f = 0; f < 4; f++) mma_tf32(sacc[f], qf[s], bf[f]);
        }
#pragma unroll
        for (int f = 0; f < 4; f++)
#pragma unroll
            for (int e = 0; e < 4; e++) sacc[f][e] *= C_SM;

        float mt0 = sacc[0][0], mt1 = sacc[0][2];
#pragma unroll
        for (int f = 0; f < 4; f++) {
            mt0 = fmaxf(mt0, fmaxf(sacc[f][0], sacc[f][1]));
            mt1 = fmaxf(mt1, fmaxf(sacc[f][2], sacc[f][3]));
        }
        mt0 = fmaxf(mt0, __shfl_xor_sync(0xffffffffu, mt0, 1));
        mt0 = fmaxf(mt0, __shfl_xor_sync(0xffffffffu, mt0, 2));
        mt1 = fmaxf(mt1, __shfl_xor_sync(0xffffffffu, mt1, 1));
        mt1 = fmaxf(mt1, __shfl_xor_sync(0xffffffffu, mt1, 2));

        float mn0 = fmaxf(m_[0], mt0), mn1 = fmaxf(m_[1], mt1);
        float al0 = exp2f(m_[0] - mn0), al1 = exp2f(m_[1] - mn1);
        m_[0] = mn0; m_[1] = mn1;

        float ls0 = 0.f, ls1 = 0.f;
#pragma unroll
        for (int f = 0; f < 4; f++) {
            sacc[f][0] = exp2f(sacc[f][0] - mn0);
            sacc[f][1] = exp2f(sacc[f][1] - mn0);
            sacc[f][2] = exp2f(sacc[f][2] - mn1);
            sacc[f][3] = exp2f(sacc[f][3] - mn1);
            ls0 += sacc[f][0] + sacc[f][1];
            ls1 += sacc[f][2] + sacc[f][3];
        }
        ls0 += __shfl_xor_sync(0xffffffffu, ls0, 1);
        ls0 += __shfl_xor_sync(0xffffffffu, ls0, 2);
        ls1 += __shfl_xor_sync(0xffffffffu, ls1, 1);
        ls1 += __shfl_xor_sync(0xffffffffu, ls1, 2);
        l_[0] = l_[0] * al0 + ls0;
        l_[1] = l_[1] * al1 + ls1;
#pragma unroll
        for (int f = 0; f < 8; f++) {
            oacc[f][0] *= al0; oacc[f][1] *= al0;
            oacc[f][2] *= al1; oacc[f][3] *= al1;
        }

#pragma unroll
        for (int f = 0; f < 4; f++) {
            int c0 = 8 * f + 2 * q4;
            Pp[r0 * 36 + c0]     = f2tf(sacc[f][0]);
            Pp[r0 * 36 + c0 + 1] = f2tf(sacc[f][1]);
            Pp[r1 * 36 + c0]     = f2tf(sacc[f][2]);
            Pp[r1 * 36 + c0 + 1] = f2tf(sacc[f][3]);
        }
        __syncwarp();

#pragma unroll
        for (int s = 0; s < 4; s++) {
            uint32_t pa[4];
            pa[0] = Pp[r0 * 36 + q4 + 8 * s];
            pa[1] = Pp[r1 * 36 + q4 + 8 * s];
            pa[2] = Pp[r0 * 36 + q4 + 4 + 8 * s];
            pa[3] = Pp[r1 * 36 + q4 + 4 + 8 * s];
#pragma unroll
            for (int f = 0; f < 8; f++) {
                uint32_t vb[2];
                vb[0] = Vs[(8 * s + q4) * 68 + 8 * f + g];
                vb[1] = Vs[(8 * s + q4 + 4) * 68 + 8 * f + g];
                mma_tf32(oacc[f], pa, vb);
            }
        }
        __syncthreads();
        if (kt + 2 < 32) { ATT_STAGE_LOAD(cur, (kt + 2) * 32); CP_COMMIT(); }
    }

    // ---- finalize: O /= l ; write bf16 hi/lo row-major [b*t][h*64+hd] ----
    float inv0 = 1.f / l_[0], inv1 = 1.f / l_[1];
#pragma unroll
    for (int f = 0; f < 8; f++) {
        int c = 8 * f + 2 * q4;
        size_t i0 = ((size_t)b * T_ + q0 + r0) * D_ + h * HD_ + c;
        size_t i1 = ((size_t)b * T_ + q0 + r1) * D_ + h * HD_ + c;
        float v00 = oacc[f][0] * inv0, v01 = oacc[f][1] * inv0;
        float v10 = oacc[f][2] * inv1, v11 = oacc[f][3] * inv1;
        __nv_bfloat16 h00,l00,h01,l01,h10,l10,h11,l11;
        bfsplit(v00,h00,l00); bfsplit(v01,h01,l01);
        bfsplit(v10,h10,l10); bfsplit(v11,h11,l11);
        *(__nv_bfloat162*)(g_oh + i0) = {h00, h01};
        *(__nv_bfloat162*)(g_ol + i0) = {l00, l01};
        *(__nv_bfloat162*)(g_oh + i1) = {h10, h11};
        *(__nv_bfloat162*)(g_ol + i1) = {l10, l11};
    }
}

// ============================================================
// O-proj GEMM, bf16 3-term (Ah.Bh + Ah.Bl + Al.Bh) with ldmatrix.
// A hi/lo [8192][768] bf16 row-major; B = Wo^T hi/lo [768][768] bf16 [n][k].
// BM=128 BN=128 BK=32, 2-stage cp.async ring, 256 thr (8 warps 2m x 4n).
// smem row stride 40 b16 (80 B); stage = 4 x 128 x 80 = 40960 B.
// ============================================================
#define OB_STAGE 40960
__global__ __launch_bounds__(256, 2)
void gemm_o_bf16(const __nv_bfloat16* __restrict__ Ah, const __nv_bfloat16* __restrict__ Al,
                 const __nv_bfloat16* __restrict__ Bh, const __nv_bfloat16* __restrict__ Bl,
                 const float* __restrict__ bias, float* __restrict__ out)
{
    extern __shared__ char smo[];
    const int tid = threadIdx.x;
    const int w = tid >> 5, lane = tid & 31, g = lane >> 2, q4 = lane & 3;
    const int wm = (w & 1) * 64, wn = (w >> 1) * 32;
    const int row0 = blockIdx.x * 128, col0 = blockIdx.y * 128;

    float acc[4][4][4];
#pragma unroll
    for (int i = 0; i < 4; i++)
#pragma unroll
        for (int f = 0; f < 4; f++)
#pragma unroll
            for (int e = 0; e < 4; e++) acc[i][f][e] = 0.f;

    // ldmatrix base addresses (per-thread), offsets within a stage:
    //   Ah 0, Al 10240, Bh 20480, Bl 30720
    const int lrow = lane & 15;
    const int lchk = (lane >> 4) * 16;   // 0 or 16 bytes

#define OB_STAGE_LOAD(s, k0) do {                                              \
    char* base_ = smo + (s) * OB_STAGE;                                        \
    _Pragma("unroll")                                                          \
    for (int i = 0; i < 2; i++) {                                              \
        int idx = tid + i * 256;                                               \
        int r = idx >> 2, ch = idx & 3;                                        \
        uint32_t so = saddr(base_ + r * 80 + ch * 16);                         \
        cp16(so,         Ah + (size_t)(row0 + r) * D_ + (k0) + ch * 8);        \
        cp16(so + 10240, Al + (size_t)(row0 + r) * D_ + (k0) + ch * 8);        \
        cp16(so + 20480, Bh + (size_t)(col0 + r) * D_ + (k0) + ch * 8);        \
        cp16(so + 30720, Bl + (size_t)(col0 + r) * D_ + (k0) + ch * 8);        \
    } } while (0)

    OB_STAGE_LOAD(0, 0);  CP_COMMIT();
    OB_STAGE_LOAD(1, 32); CP_COMMIT();

    for (int kb = 0; kb < 24; kb++) {
        if (kb + 1 < 24) CP_WAIT1(); else CP_WAIT0();
        __syncthreads();
        char* base = smo + (kb & 1) * OB_STAGE;
#pragma unroll
        for (int ks = 0; ks < 2; ks++) {
            uint32_t ah[4][4], al[4][4];
#pragma unroll
            for (int i = 0; i < 4; i++) {
                uint32_t a = saddr(base + (wm + 16 * i + lrow) * 80 + ks * 32 + lchk);
                LDSM_X4(ah[i], a);
                LDSM_X4(al[i], a + 10240);
            }
            uint32_t bh4[2][4], bl4[2][4];
#pragma unroll
            for (int j = 0; j < 2; j++) {
                uint32_t a = saddr(base + 20480 + (wn + 16 * j + lrow) * 80 + ks * 32 + lchk);
                LDSM_X4(bh4[j], a);
                LDSM_X4(bl4[j], a + 10240);
            }
#pragma unroll
            for (int i = 0; i < 4; i++)
#pragma unroll
                for (int f = 0; f < 4; f++) {
                    uint32_t bhf[2] = { bh4[f >> 1][f & 1], bh4[f >> 1][(f & 1) + 2] };
                    uint32_t blf[2] = { bl4[f >> 1][f & 1], bl4[f >> 1][(f & 1) + 2] };
                    mma_bf16(acc[i][f], ah[i], bhf);
                    mma_bf16(acc[i][f], ah[i], blf);
                    mma_bf16(acc[i][f], al[i], bhf);
                }
        }
        __syncthreads();
        if (kb + 2 < 24) { OB_STAGE_LOAD(kb & 1, (kb + 2) * 32); CP_COMMIT(); }
    }

#pragma unroll
    for (int i = 0; i < 4; i++)
#pragma unroll
        for (int f = 0; f < 4; f++) {
            int col = col0 + wn + 8 * f + 2 * q4;
            float b0 = bias[col], b1 = bias[col + 1];
#pragma unroll
            for (int half = 0; half < 2; half++) {
                int row = row0 + wm + 16 * i + g + 8 * half;
                float2 v;
                v.x = acc[i][f][2 * half + 0] + b0;
                v.y = acc[i][f][2 * half + 1] + b1;
                *(float2*)(out + (size_t)row * D_ + col) = v;
            }
        }
}

// ============================================================
extern "C" void kernel_launch(void* const* d_in, const int* in_sizes, int n_in,
                              void* d_out, int out_size)
{
    const float* x         = (const float*)d_in[0];
    const float* attn_mask = (const float*)d_in[1];
    const float* rel_bias  = (const float*)d_in[2];
    const float* Wq = (const float*)d_in[3];
    const float* bq = (const float*)d_in[4];
    const float* Wk = (const float*)d_in[5];
    const float* bk = (const float*)d_in[6];
    const float* Wv = (const float*)d_in[7];
    const float* bv = (const float*)d_in[8];
    const float* Wo = (const float*)d_in[9];
    const float* bo = (const float*)d_in[10];
    const float* Wg = (const float*)d_in[11];
    const float* bg = (const float*)d_in[12];
    const float* grep_a = (const float*)d_in[13];
    float* out = (float*)d_out;

    uint32_t *xhi, *wqh, *wkh, *wvh, *q, *k, *v;
    __nv_bfloat16 *woth, *wotl, *oh, *ol;
    float *ga1;
    cudaGetSymbolAddress((void**)&xhi,  g_xhi);
    cudaGetSymbolAddress((void**)&wqh,  g_wqh);
    cudaGetSymbolAddress((void**)&wkh,  g_wkh);
    cudaGetSymbolAddress((void**)&wvh,  g_wvh);
    cudaGetSymbolAddress((void**)&woth, g_woth);
    cudaGetSymbolAddress((void**)&wotl, g_wotl);
    cudaGetSymbolAddress((void**)&q,    g_q);
    cudaGetSymbolAddress((void**)&k,    g_k);
    cudaGetSymbolAddress((void**)&v,    g_v);
    cudaGetSymbolAddress((void**)&oh,   g_oh);
    cudaGetSymbolAddress((void**)&ol,   g_ol);
    cudaGetSymbolAddress((void**)&ga1,  g_ga1);

    cudaFuncSetAttribute(gemm_qkv,    cudaFuncAttributeMaxDynamicSharedMemorySize, QKV_STAGE * 3 * 4);
    cudaFuncSetAttribute(attn_kernel, cudaFuncAttributeMaxDynamicSharedMemorySize, 91136);
    cudaFuncSetAttribute(gemm_o_bf16, cudaFuncAttributeMaxDynamicSharedMemorySize, OB_STAGE * 2);

    const int nx4 = N_ * D_ / 4;
    const int nw4 = D_ * D_ / 4;
    // launch order: attn_kernel is the 6th launch (ncu -s 5 -c 1)
    conv_x<<<(nx4 + 255) / 256, 256>>>((const float4*)x, (uint4*)xhi, nx4, Wg, bg);   // 0
    conv_w3<<<dim3((nw4 + 255) / 256, 1, 3), 256>>>(                                   // 1
        (const float4*)Wq, (const float4*)Wk, (const float4*)Wv,
        (uint4*)wqh, (uint4*)wkh, (uint4*)wvh, nw4);
    conv_woT<<<dim3(24, 24), dim3(32, 32)>>>(Wo, woth, wotl);                          // 2
    gates_kernel<<<BH_ * T_ / 8, 256>>>(x, grep_a, ga1);                               // 3
    gemm_qkv<<<dim3(64, 6, 3), 256, QKV_STAGE * 3 * 4>>>(                              // 4
        xhi, wqh, wkh, wvh, bq, bk, bv, q, k, v);
    attn_kernel<<<dim3(T_ / 128, BH_), 256, 91136>>>(rel_bias, attn_mask);             // 5
    gemm_o_bf16<<<dim3(64, 6), 256, OB_STAGE * 2>>>(oh, ol, woth, wotl, bo, out);      // 6
}